// round 8
// baseline (speedup 1.0000x reference)
#include <cuda_runtime.h>
#include <cuda_bf16.h>
#include <cstdint>

// Problem constants
#define CB 16
#define CC 64
#define CH 128
#define CW 128
#define CN (CH*CW)
#define PLANE ((long)CC*CN)
#define TOTE 16777216

// -------- scratch (device globals) --------
__device__ float          g_v[2][TOTE];     // V fp32 (pre-transpose)
__device__ __nv_bfloat16  g_qb[2][TOTE];    // Q bf16 [h,w]
__device__ __nv_bfloat16  g_kb[2][TOTE];    // K bf16 [g,w]
__device__ __nv_bfloat16  g_vth[2][TOTE];   // V^T hi bf16 [w,g]
__device__ __nv_bfloat16  g_vtl[2][TOTE];   // V^T lo bf16 [w,g]
__device__ float          g_fused[TOTE];
__device__ float          g_psum[CB*CC];
__device__ float          g_psumsq[CB*CC];
__device__ float          g_scale[CC];
__device__ float          g_shift[CC];

// ============================================================
// mma.sync helpers (sm_80+ PTX; safe on generic compute_103 target)
// ============================================================
__device__ __forceinline__ void mma_bf16(float d[4],
                                         uint32_t a0, uint32_t a1, uint32_t a2, uint32_t a3,
                                         uint32_t b0, uint32_t b1)
{
    asm volatile(
        "mma.sync.aligned.m16n8k16.row.col.f32.bf16.bf16.f32 "
        "{%0,%1,%2,%3}, {%4,%5,%6,%7}, {%8,%9}, {%0,%1,%2,%3};"
        : "+f"(d[0]), "+f"(d[1]), "+f"(d[2]), "+f"(d[3])
        : "r"(a0), "r"(a1), "r"(a2), "r"(a3), "r"(b0), "r"(b1));
}

__device__ __forceinline__ uint32_t ld32(const __nv_bfloat16* p) {
    return *reinterpret_cast<const uint32_t*>(p);
}

__device__ __forceinline__ uint32_t packbf(__nv_bfloat16 lo, __nv_bfloat16 hi) {
    return (uint32_t)__bfloat16_as_ushort(lo) | ((uint32_t)__bfloat16_as_ushort(hi) << 16);
}

// split (x,y) into bf16 hi pair + bf16 residual pair (x -> low half = even col)
__device__ __forceinline__ void split2(float x, float y, uint32_t& hi, uint32_t& lo) {
    __nv_bfloat16 hx = __float2bfloat16(x), hy = __float2bfloat16(y);
    float rx = x - __bfloat162float(hx);
    float ry = y - __bfloat162float(hy);
    hi = packbf(hx, hy);
    lo = packbf(__float2bfloat16(rx), __float2bfloat16(ry));
}

// ============================================================
// Projection (SIMT fp32): Q,K -> bf16, V -> fp32
// ============================================================
__device__ __forceinline__ void proj_one_b(const float* __restrict__ ws,
                                           const float* __restrict__ bias,
                                           const float col[64],
                                           __nv_bfloat16* __restrict__ out, long base)
{
#pragma unroll 2
    for (int og = 0; og < 64; og += 8) {
        float acc[8];
#pragma unroll
        for (int j = 0; j < 8; j++) acc[j] = __ldg(bias + og + j);
#pragma unroll
        for (int c4 = 0; c4 < 16; c4++) {
#pragma unroll
            for (int j = 0; j < 8; j++) {
                float4 w4 = *reinterpret_cast<const float4*>(ws + (og + j) * 64 + c4 * 4);
                acc[j] = fmaf(w4.x, col[c4*4+0], acc[j]);
                acc[j] = fmaf(w4.y, col[c4*4+1], acc[j]);
                acc[j] = fmaf(w4.z, col[c4*4+2], acc[j]);
                acc[j] = fmaf(w4.w, col[c4*4+3], acc[j]);
            }
        }
#pragma unroll
        for (int j = 0; j < 8; j++) out[base + (long)(og + j) * CN] = __float2bfloat16(acc[j]);
    }
}
__device__ __forceinline__ void proj_one_f(const float* __restrict__ ws,
                                           const float* __restrict__ bias,
                                           const float col[64],
                                           float* __restrict__ out, long base)
{
#pragma unroll 2
    for (int og = 0; og < 64; og += 8) {
        float acc[8];
#pragma unroll
        for (int j = 0; j < 8; j++) acc[j] = __ldg(bias + og + j);
#pragma unroll
        for (int c4 = 0; c4 < 16; c4++) {
#pragma unroll
            for (int j = 0; j < 8; j++) {
                float4 w4 = *reinterpret_cast<const float4*>(ws + (og + j) * 64 + c4 * 4);
                acc[j] = fmaf(w4.x, col[c4*4+0], acc[j]);
                acc[j] = fmaf(w4.y, col[c4*4+1], acc[j]);
                acc[j] = fmaf(w4.z, col[c4*4+2], acc[j]);
                acc[j] = fmaf(w4.w, col[c4*4+3], acc[j]);
            }
        }
#pragma unroll
        for (int j = 0; j < 8; j++) out[base + (long)(og + j) * CN] = acc[j];
    }
}

__global__ void proj_kernel(const float* __restrict__ x, const float* __restrict__ rssi,
                            const float* __restrict__ qw, const float* __restrict__ qb,
                            const float* __restrict__ kw, const float* __restrict__ kb,
                            const float* __restrict__ vw, const float* __restrict__ vb,
                            int branch)
{
    extern __shared__ float sw[];
    float* swq = sw;  float* swk = sw + 4096;  float* swv = sw + 8192;
    int t = threadIdx.x;
    for (int i = t; i < 4096; i += 256) { swq[i] = qw[i]; swk[i] = kw[i]; swv[i] = vw[i]; }
    __syncthreads();

    int b = blockIdx.y;
    int n = blockIdx.x * 256 + t;
    long base = (long)b * PLANE + n;
    float col[64];

#pragma unroll
    for (int c = 0; c < 64; c++) col[c] = rssi[base + (long)c * CN];
    proj_one_b(swq, qb, col, g_qb[branch], base);

#pragma unroll
    for (int c = 0; c < 64; c++) col[c] = x[base + (long)c * CN];
    proj_one_b(swk, kb, col, g_kb[branch], base);
    proj_one_f(swv, vb, col, g_v[branch], base);
}

// ============================================================
// V transpose + bf16 split: g_v [g,w] fp32 -> g_vth/g_vtl [w,g] bf16
// ============================================================
__global__ void vsplit_kernel()
{
    __shared__ float T[32][129];
    int bc = blockIdx.x, br = blockIdx.y;
    int t = threadIdx.x;
    const float* V = g_v[br] + (long)bc * CN;
    __nv_bfloat16* Oh = g_vth[br] + (long)bc * CN;
    __nv_bfloat16* Ol = g_vtl[br] + (long)bc * CN;
    int w = t >> 1, half = t & 1;

    for (int s = 0; s < 4; s++) {
        __syncthreads();
#pragma unroll
        for (int i = 0; i < 16; i++) {
            int idx = t + i * 256;
            T[idx >> 7][idx & 127] = V[(s * 32 + (idx >> 7)) * 128 + (idx & 127)];
        }
        __syncthreads();
        uint32_t ph[8], pl[8];
#pragma unroll
        for (int j = 0; j < 8; j++) {
            float v0 = T[half * 16 + 2*j    ][w];
            float v1 = T[half * 16 + 2*j + 1][w];
            __nv_bfloat16 h0 = __float2bfloat16(v0);
            __nv_bfloat16 h1 = __float2bfloat16(v1);
            __nv_bfloat16 l0 = __float2bfloat16(v0 - __bfloat162float(h0));
            __nv_bfloat16 l1 = __float2bfloat16(v1 - __bfloat162float(h1));
            ph[j] = packbf(h0, h1);
            pl[j] = packbf(l0, l1);
        }
        long ob = (long)w * 128 + s * 32 + half * 16;
        reinterpret_cast<uint4*>(Oh + ob)[0] = make_uint4(ph[0], ph[1], ph[2], ph[3]);
        reinterpret_cast<uint4*>(Oh + ob)[1] = make_uint4(ph[4], ph[5], ph[6], ph[7]);
        reinterpret_cast<uint4*>(Ol + ob)[0] = make_uint4(pl[0], pl[1], pl[2], pl[3]);
        reinterpret_cast<uint4*>(Ol + ob)[1] = make_uint4(pl[4], pl[5], pl[6], pl[7]);
    }
}

// ============================================================
// Attention via mma.sync bf16: 1 CTA per (b,c), 8 warps x 16 rows.
// GEMM1 plain bf16; GEMM2 split-bf16 (3 products). O accumulates both branches.
// ============================================================
__global__ __launch_bounds__(256, 1) void attn_kernel()
{
    int t = threadIdx.x, lane = t & 31, wid = t >> 5;
    int q = lane & 3, gid = lane >> 2;
    int bc = blockIdx.x;
    long base = (long)bc * CN;
    const float sc = 0.088388347648318447f;  // 1/sqrt(128)
    int r0 = wid * 16 + gid;                 // row of fragment group (r1 = r0+8)

    float oacc[16][4];
#pragma unroll
    for (int nt = 0; nt < 16; nt++)
#pragma unroll
        for (int j = 0; j < 4; j++) oacc[nt][j] = 0.f;

#pragma unroll 1
    for (int br = 0; br < 2; br++) {
        const __nv_bfloat16* Qp = g_qb[br] + base;
        const __nv_bfloat16* Kp = g_kb[br] + base;
        const __nv_bfloat16* VH = g_vth[br] + base;
        const __nv_bfloat16* VL = g_vtl[br] + base;

        // ---- GEMM1: S = Q K^T (bf16, f32 accum) ----
        float sacc[16][4];
#pragma unroll
        for (int nt = 0; nt < 16; nt++)
#pragma unroll
            for (int j = 0; j < 4; j++) sacc[nt][j] = 0.f;

#pragma unroll
        for (int st = 0; st < 8; st++) {
            int c0 = st * 16 + q * 2;
            uint32_t a0 = ld32(Qp + (long)r0 * 128 + c0);
            uint32_t a1 = ld32(Qp + (long)(r0 + 8) * 128 + c0);
            uint32_t a2 = ld32(Qp + (long)r0 * 128 + c0 + 8);
            uint32_t a3 = ld32(Qp + (long)(r0 + 8) * 128 + c0 + 8);
#pragma unroll
            for (int nt = 0; nt < 16; nt++) {
                const __nv_bfloat16* kr = Kp + (long)(nt * 8 + gid) * 128 + c0;
                mma_bf16(sacc[nt], a0, a1, a2, a3, ld32(kr), ld32(kr + 8));
            }
        }

        // ---- softmax on fragments (rows r0: c0/c1, r1: c2/c3) ----
        float m0 = -1e30f, m1 = -1e30f;
#pragma unroll
        for (int nt = 0; nt < 16; nt++) {
            m0 = fmaxf(m0, fmaxf(sacc[nt][0], sacc[nt][1]));
            m1 = fmaxf(m1, fmaxf(sacc[nt][2], sacc[nt][3]));
        }
        m0 = fmaxf(m0, __shfl_xor_sync(0xffffffffu, m0, 1));
        m0 = fmaxf(m0, __shfl_xor_sync(0xffffffffu, m0, 2));
        m1 = fmaxf(m1, __shfl_xor_sync(0xffffffffu, m1, 1));
        m1 = fmaxf(m1, __shfl_xor_sync(0xffffffffu, m1, 2));

        float s0 = 0.f, s1 = 0.f;
#pragma unroll
        for (int nt = 0; nt < 16; nt++) {
            sacc[nt][0] = __expf((sacc[nt][0] - m0) * sc);
            sacc[nt][1] = __expf((sacc[nt][1] - m0) * sc);
            sacc[nt][2] = __expf((sacc[nt][2] - m1) * sc);
            sacc[nt][3] = __expf((sacc[nt][3] - m1) * sc);
            s0 += sacc[nt][0] + sacc[nt][1];
            s1 += sacc[nt][2] + sacc[nt][3];
        }
        s0 += __shfl_xor_sync(0xffffffffu, s0, 1);
        s0 += __shfl_xor_sync(0xffffffffu, s0, 2);
        s1 += __shfl_xor_sync(0xffffffffu, s1, 1);
        s1 += __shfl_xor_sync(0xffffffffu, s1, 2);
        float inv0 = 1.f / s0, inv1 = 1.f / s1;

        // repack C-frags -> A-frags (bf16 hi/lo split), k-step st covers tiles 2st,2st+1
        uint32_t phi[8][4], plo[8][4];
#pragma unroll
        for (int st = 0; st < 8; st++) {
            split2(sacc[2*st  ][0] * inv0, sacc[2*st  ][1] * inv0, phi[st][0], plo[st][0]);
            split2(sacc[2*st  ][2] * inv1, sacc[2*st  ][3] * inv1, phi[st][1], plo[st][1]);
            split2(sacc[2*st+1][0] * inv0, sacc[2*st+1][1] * inv0, phi[st][2], plo[st][2]);
            split2(sacc[2*st+1][2] * inv1, sacc[2*st+1][3] * inv1, phi[st][3], plo[st][3]);
        }

        // ---- GEMM2: O += Phi*Vhi + Phi*Vlo + Plo*Vhi ----
#pragma unroll
        for (int pass = 0; pass < 3; pass++) {
            const __nv_bfloat16* Vp = (pass == 1) ? VL : VH;
#pragma unroll
            for (int st = 0; st < 8; st++) {
                uint32_t a0 = (pass == 2) ? plo[st][0] : phi[st][0];
                uint32_t a1 = (pass == 2) ? plo[st][1] : phi[st][1];
                uint32_t a2 = (pass == 2) ? plo[st][2] : phi[st][2];
                uint32_t a3 = (pass == 2) ? plo[st][3] : phi[st][3];
                int g0 = st * 16 + q * 2;
#pragma unroll
                for (int nt = 0; nt < 16; nt++) {
                    const __nv_bfloat16* vr = Vp + (long)(nt * 8 + gid) * 128 + g0;
                    mma_bf16(oacc[nt], a0, a1, a2, a3, ld32(vr), ld32(vr + 8));
                }
            }
        }
    }

    // ---- epilogue: fused write + BN partials ----
    float lsum = 0.f, lsq = 0.f;
    float* F = g_fused + base;
#pragma unroll
    for (int nt = 0; nt < 16; nt++) {
        int c = nt * 8 + q * 2;
        float2 u = make_float2(oacc[nt][0], oacc[nt][1]);
        float2 v = make_float2(oacc[nt][2], oacc[nt][3]);
        *reinterpret_cast<float2*>(F + (long)r0 * 128 + c) = u;
        *reinterpret_cast<float2*>(F + (long)(r0 + 8) * 128 + c) = v;
        lsum += u.x + u.y + v.x + v.y;
        lsq  += u.x*u.x + u.y*u.y + v.x*v.x + v.y*v.y;
    }
#pragma unroll
    for (int o = 16; o; o >>= 1) {
        lsum += __shfl_xor_sync(0xffffffffu, lsum, o);
        lsq  += __shfl_xor_sync(0xffffffffu, lsq , o);
    }
    __shared__ float red[16];
    if (lane == 0) { red[wid] = lsum; red[8 + wid] = lsq; }
    __syncthreads();
    if (t == 0) {
        float s = 0.f, qq = 0.f;
        for (int w2 = 0; w2 < 8; w2++) { s += red[w2]; qq += red[8 + w2]; }
        g_psum[bc] = s; g_psumsq[bc] = qq;
    }
}

// ============================================================
// BN stats + normalize
// ============================================================
__global__ void stats_kernel(const float* __restrict__ gamma, const float* __restrict__ beta)
{
    int c = threadIdx.x;
    if (c < CC) {
        double s = 0.0, q = 0.0;
        for (int b = 0; b < CB; b++) {
            s += (double)g_psum[b * CC + c];
            q += (double)g_psumsq[b * CC + c];
        }
        double nn = (double)CB * (double)CN;
        double mean = s / nn;
        double var = q / nn - mean * mean;
        float a = (float)((double)gamma[c] * rsqrt(var + 1e-5));
        g_scale[c] = a;
        g_shift[c] = beta[c] - (float)mean * a;
    }
}

__global__ void norm_kernel(float* __restrict__ out)
{
    long i4 = (long)blockIdx.x * blockDim.x + threadIdx.x;
    if (i4 < (TOTE / 4)) {
        int c = (int)((i4 >> 12) & 63);
        float a = g_scale[c], sh = g_shift[c];
        float4 f = reinterpret_cast<const float4*>(g_fused)[i4];
        float4 r;
        r.x = fmaxf(0.f, fmaf(f.x, a, sh));
        r.y = fmaxf(0.f, fmaf(f.y, a, sh));
        r.z = fmaxf(0.f, fmaf(f.z, a, sh));
        r.w = fmaxf(0.f, fmaf(f.w, a, sh));
        reinterpret_cast<float4*>(out)[i4] = r;
    }
}

// ============================================================
// Launch
// ============================================================
#define PROJ_SMEM (3*4096*4)

extern "C" void kernel_launch(void* const* d_in, const int* in_sizes, int n_in,
                              void* d_out, int out_size)
{
    const float* x1    = (const float*)d_in[0];
    const float* x2    = (const float*)d_in[1];
    const float* rssi1 = (const float*)d_in[2];
    const float* rssi2 = (const float*)d_in[3];
    const float* qw    = (const float*)d_in[4];
    const float* qb    = (const float*)d_in[5];
    const float* kw    = (const float*)d_in[6];
    const float* kb    = (const float*)d_in[7];
    const float* vw    = (const float*)d_in[8];
    const float* vb    = (const float*)d_in[9];
    const float* gamma = (const float*)d_in[10];
    const float* beta  = (const float*)d_in[11];
    float* out = (float*)d_out;

    cudaFuncSetAttribute(proj_kernel, cudaFuncAttributeMaxDynamicSharedMemorySize, PROJ_SMEM);

    dim3 pg(CN / 256, CB);
    proj_kernel<<<pg, 256, PROJ_SMEM>>>(x1, rssi1, qw, qb, kw, kb, vw, vb, 0);
    proj_kernel<<<pg, 256, PROJ_SMEM>>>(x2, rssi2, qw, qb, kw, kb, vw, vb, 1);
    vsplit_kernel<<<dim3(CB * CC, 2), 256>>>();
    attn_kernel<<<CB * CC, 256>>>();
    stats_kernel<<<1, 64>>>(gamma, beta);
    norm_kernel<<<TOTE / 4 / 256, 256>>>(out);
}

// round 9
// speedup vs baseline: 1.4808x; 1.4808x over previous
#include <cuda_runtime.h>
#include <cuda_bf16.h>
#include <cstdint>

// Problem constants
#define CB 16
#define CC 64
#define CH 128
#define CW 128
#define CN (CH*CW)
#define PLANE ((long)CC*CN)
#define TOTE 16777216

// -------- scratch (device globals) --------
__device__ float          g_v[2][TOTE];     // V fp32 (pre-transpose)
__device__ __nv_bfloat16  g_qb[2][TOTE];    // Q bf16 [h,w]
__device__ __nv_bfloat16  g_kb[2][TOTE];    // K bf16 [g,w]
__device__ __nv_bfloat16  g_vth[2][TOTE];   // V^T hi bf16 [w,g]
__device__ __nv_bfloat16  g_vtl[2][TOTE];   // V^T lo bf16 [w,g]
__device__ float          g_fused[TOTE];
__device__ float          g_psum[CB*CC];
__device__ float          g_psumsq[CB*CC];
__device__ float          g_scale[CC];
__device__ float          g_shift[CC];

// ============================================================
// mma.sync / ldmatrix helpers (sm_80 PTX; safe on generic compute_103)
// ============================================================
__device__ __forceinline__ void mma_bf16(float d[4],
                                         uint32_t a0, uint32_t a1, uint32_t a2, uint32_t a3,
                                         uint32_t b0, uint32_t b1)
{
    asm volatile(
        "mma.sync.aligned.m16n8k16.row.col.f32.bf16.bf16.f32 "
        "{%0,%1,%2,%3}, {%4,%5,%6,%7}, {%8,%9}, {%0,%1,%2,%3};"
        : "+f"(d[0]), "+f"(d[1]), "+f"(d[2]), "+f"(d[3])
        : "r"(a0), "r"(a1), "r"(a2), "r"(a3), "r"(b0), "r"(b1));
}

__device__ __forceinline__ void ldmx4(uint32_t& b0, uint32_t& b1, uint32_t& b2, uint32_t& b3,
                                      uint32_t addr)
{
    asm volatile("ldmatrix.sync.aligned.m8n8.x4.shared.b16 {%0,%1,%2,%3}, [%4];"
                 : "=r"(b0), "=r"(b1), "=r"(b2), "=r"(b3) : "r"(addr));
}

__device__ __forceinline__ uint32_t smem_to_u32(const void* p) {
    uint32_t a;
    asm("{ .reg .u64 tmp; cvta.to.shared.u64 tmp, %1; cvt.u32.u64 %0, tmp; }" : "=r"(a) : "l"(p));
    return a;
}

__device__ __forceinline__ uint32_t ld32(const __nv_bfloat16* p) {
    return *reinterpret_cast<const uint32_t*>(p);
}

__device__ __forceinline__ uint32_t packbf(__nv_bfloat16 lo, __nv_bfloat16 hi) {
    return (uint32_t)__bfloat16_as_ushort(lo) | ((uint32_t)__bfloat16_as_ushort(hi) << 16);
}

// split (x,y) into bf16 hi pair + bf16 residual pair
__device__ __forceinline__ void split2(float x, float y, uint32_t& hi, uint32_t& lo) {
    __nv_bfloat16 hx = __float2bfloat16(x), hy = __float2bfloat16(y);
    float rx = x - __bfloat162float(hx);
    float ry = y - __bfloat162float(hy);
    hi = packbf(hx, hy);
    lo = packbf(__float2bfloat16(rx), __float2bfloat16(ry));
}

// ============================================================
// Projection (SIMT fp32): Q,K -> bf16, V -> fp32
// ============================================================
__device__ __forceinline__ void proj_one_b(const float* __restrict__ ws,
                                           const float* __restrict__ bias,
                                           const float col[64],
                                           __nv_bfloat16* __restrict__ out, long base)
{
#pragma unroll 2
    for (int og = 0; og < 64; og += 8) {
        float acc[8];
#pragma unroll
        for (int j = 0; j < 8; j++) acc[j] = __ldg(bias + og + j);
#pragma unroll
        for (int c4 = 0; c4 < 16; c4++) {
#pragma unroll
            for (int j = 0; j < 8; j++) {
                float4 w4 = *reinterpret_cast<const float4*>(ws + (og + j) * 64 + c4 * 4);
                acc[j] = fmaf(w4.x, col[c4*4+0], acc[j]);
                acc[j] = fmaf(w4.y, col[c4*4+1], acc[j]);
                acc[j] = fmaf(w4.z, col[c4*4+2], acc[j]);
                acc[j] = fmaf(w4.w, col[c4*4+3], acc[j]);
            }
        }
#pragma unroll
        for (int j = 0; j < 8; j++) out[base + (long)(og + j) * CN] = __float2bfloat16(acc[j]);
    }
}
__device__ __forceinline__ void proj_one_f(const float* __restrict__ ws,
                                           const float* __restrict__ bias,
                                           const float col[64],
                                           float* __restrict__ out, long base)
{
#pragma unroll 2
    for (int og = 0; og < 64; og += 8) {
        float acc[8];
#pragma unroll
        for (int j = 0; j < 8; j++) acc[j] = __ldg(bias + og + j);
#pragma unroll
        for (int c4 = 0; c4 < 16; c4++) {
#pragma unroll
            for (int j = 0; j < 8; j++) {
                float4 w4 = *reinterpret_cast<const float4*>(ws + (og + j) * 64 + c4 * 4);
                acc[j] = fmaf(w4.x, col[c4*4+0], acc[j]);
                acc[j] = fmaf(w4.y, col[c4*4+1], acc[j]);
                acc[j] = fmaf(w4.z, col[c4*4+2], acc[j]);
                acc[j] = fmaf(w4.w, col[c4*4+3], acc[j]);
            }
        }
#pragma unroll
        for (int j = 0; j < 8; j++) out[base + (long)(og + j) * CN] = acc[j];
    }
}

__global__ void proj_kernel(const float* __restrict__ x, const float* __restrict__ rssi,
                            const float* __restrict__ qw, const float* __restrict__ qb,
                            const float* __restrict__ kw, const float* __restrict__ kb,
                            const float* __restrict__ vw, const float* __restrict__ vb,
                            int branch)
{
    extern __shared__ float sw[];
    float* swq = sw;  float* swk = sw + 4096;  float* swv = sw + 8192;
    int t = threadIdx.x;
    for (int i = t; i < 4096; i += 256) { swq[i] = qw[i]; swk[i] = kw[i]; swv[i] = vw[i]; }
    __syncthreads();

    int b = blockIdx.y;
    int n = blockIdx.x * 256 + t;
    long base = (long)b * PLANE + n;
    float col[64];

#pragma unroll
    for (int c = 0; c < 64; c++) col[c] = rssi[base + (long)c * CN];
    proj_one_b(swq, qb, col, g_qb[branch], base);

#pragma unroll
    for (int c = 0; c < 64; c++) col[c] = x[base + (long)c * CN];
    proj_one_b(swk, kb, col, g_kb[branch], base);
    proj_one_f(swv, vb, col, g_v[branch], base);
}

// ============================================================
// V transpose + bf16 split: g_v [g,w] fp32 -> g_vth/g_vtl [w,g] bf16
// ============================================================
__global__ void vsplit_kernel()
{
    __shared__ float T[32][129];
    int bc = blockIdx.x, br = blockIdx.y;
    int t = threadIdx.x;
    const float* V = g_v[br] + (long)bc * CN;
    __nv_bfloat16* Oh = g_vth[br] + (long)bc * CN;
    __nv_bfloat16* Ol = g_vtl[br] + (long)bc * CN;
    int w = t >> 1, half = t & 1;

    for (int s = 0; s < 4; s++) {
        __syncthreads();
#pragma unroll
        for (int i = 0; i < 16; i++) {
            int idx = t + i * 256;
            T[idx >> 7][idx & 127] = V[(s * 32 + (idx >> 7)) * 128 + (idx & 127)];
        }
        __syncthreads();
        uint32_t ph[8], pl[8];
#pragma unroll
        for (int j = 0; j < 8; j++) {
            float v0 = T[half * 16 + 2*j    ][w];
            float v1 = T[half * 16 + 2*j + 1][w];
            __nv_bfloat16 h0 = __float2bfloat16(v0);
            __nv_bfloat16 h1 = __float2bfloat16(v1);
            __nv_bfloat16 l0 = __float2bfloat16(v0 - __bfloat162float(h0));
            __nv_bfloat16 l1 = __float2bfloat16(v1 - __bfloat162float(h1));
            ph[j] = packbf(h0, h1);
            pl[j] = packbf(l0, l1);
        }
        long ob = (long)w * 128 + s * 32 + half * 16;
        reinterpret_cast<uint4*>(Oh + ob)[0] = make_uint4(ph[0], ph[1], ph[2], ph[3]);
        reinterpret_cast<uint4*>(Oh + ob)[1] = make_uint4(ph[4], ph[5], ph[6], ph[7]);
        reinterpret_cast<uint4*>(Ol + ob)[0] = make_uint4(pl[0], pl[1], pl[2], pl[3]);
        reinterpret_cast<uint4*>(Ol + ob)[1] = make_uint4(pl[4], pl[5], pl[6], pl[7]);
    }
}

// ============================================================
// Attention via mma.sync + smem/ldmatrix operands.
// 1 CTA per (b,c), 8 warps x 16 rows. GEMM1 bf16; GEMM2 split-bf16.
// smem tiles at pitch 272B (17x16B): conflict-free staging + ldmatrix.
// ============================================================
#define PITCHB 272
#define TILEB (128*PITCHB)          // 34816 B
#define K_OFF 0
#define VH_OFF TILEB
#define VL_OFF (2*TILEB)
#define ATTN_SMEM (3*TILEB + 64)

__device__ __forceinline__ void stage_tile(const __nv_bfloat16* __restrict__ g,
                                           char* smem, int off, int t)
{
    const float4* src = reinterpret_cast<const float4*>(g);
#pragma unroll
    for (int i = 0; i < 8; i++) {
        int idx = t + i * 256;             // 2048 float4 per 128x128 bf16 tile
        int row = idx >> 4, seg = idx & 15;
        *reinterpret_cast<float4*>(smem + off + row * PITCHB + seg * 16) = src[idx];
    }
}

__global__ __launch_bounds__(256, 1) void attn_kernel()
{
    extern __shared__ char smc[];
    uint32_t smb = smem_to_u32(smc);
    int t = threadIdx.x, lane = t & 31, wid = t >> 5;
    int q = lane & 3, gid = lane >> 2;
    int bc = blockIdx.x;
    long base = (long)bc * CN;
    const float sc = 0.088388347648318447f;  // 1/sqrt(128)
    int r0 = wid * 16 + gid;

    // ldmatrix x4 per-lane addressing: m0,m1 -> ntpair low tile (cols +0,+8),
    // m2,m3 -> high tile. lrow/lcolb are lane-constant.
    int lrow  = (lane & 7) + ((lane >> 4) << 3);   // row within 16-row pair
    int lcolb = ((lane >> 3) & 1) * 16;            // byte offset for k/g +8 half

    float oacc[16][4];
#pragma unroll
    for (int nt = 0; nt < 16; nt++)
#pragma unroll
        for (int j = 0; j < 4; j++) oacc[nt][j] = 0.f;

#pragma unroll 1
    for (int br = 0; br < 2; br++) {
        const __nv_bfloat16* Qp = g_qb[br] + base;

        __syncthreads();
        stage_tile(g_kb[br]  + base, smc, K_OFF, t);
        stage_tile(g_vth[br] + base, smc, VH_OFF, t);
        stage_tile(g_vtl[br] + base, smc, VL_OFF, t);
        __syncthreads();

        // ---- GEMM1: S = Q K^T ----
        float sacc[16][4];
#pragma unroll
        for (int nt = 0; nt < 16; nt++)
#pragma unroll
            for (int j = 0; j < 4; j++) sacc[nt][j] = 0.f;

#pragma unroll
        for (int st = 0; st < 8; st++) {
            int c0 = st * 16 + q * 2;
            uint32_t a0 = ld32(Qp + (long)r0 * 128 + c0);
            uint32_t a1 = ld32(Qp + (long)(r0 + 8) * 128 + c0);
            uint32_t a2 = ld32(Qp + (long)r0 * 128 + c0 + 8);
            uint32_t a3 = ld32(Qp + (long)(r0 + 8) * 128 + c0 + 8);
            uint32_t kb = smb + K_OFF + (uint32_t)lrow * PITCHB + st * 32 + lcolb;
#pragma unroll
            for (int np = 0; np < 8; np++) {
                uint32_t b0, b1, b2, b3;
                ldmx4(b0, b1, b2, b3, kb + np * (16 * PITCHB));
                mma_bf16(sacc[2*np  ], a0, a1, a2, a3, b0, b1);
                mma_bf16(sacc[2*np+1], a0, a1, a2, a3, b2, b3);
            }
        }

        // ---- softmax on fragments (rows r0: c0/c1, r0+8: c2/c3) ----
        float m0 = -1e30f, m1 = -1e30f;
#pragma unroll
        for (int nt = 0; nt < 16; nt++) {
            m0 = fmaxf(m0, fmaxf(sacc[nt][0], sacc[nt][1]));
            m1 = fmaxf(m1, fmaxf(sacc[nt][2], sacc[nt][3]));
        }
        m0 = fmaxf(m0, __shfl_xor_sync(0xffffffffu, m0, 1));
        m0 = fmaxf(m0, __shfl_xor_sync(0xffffffffu, m0, 2));
        m1 = fmaxf(m1, __shfl_xor_sync(0xffffffffu, m1, 1));
        m1 = fmaxf(m1, __shfl_xor_sync(0xffffffffu, m1, 2));

        float s0 = 0.f, s1 = 0.f;
#pragma unroll
        for (int nt = 0; nt < 16; nt++) {
            sacc[nt][0] = __expf((sacc[nt][0] - m0) * sc);
            sacc[nt][1] = __expf((sacc[nt][1] - m0) * sc);
            sacc[nt][2] = __expf((sacc[nt][2] - m1) * sc);
            sacc[nt][3] = __expf((sacc[nt][3] - m1) * sc);
            s0 += sacc[nt][0] + sacc[nt][1];
            s1 += sacc[nt][2] + sacc[nt][3];
        }
        s0 += __shfl_xor_sync(0xffffffffu, s0, 1);
        s0 += __shfl_xor_sync(0xffffffffu, s0, 2);
        s1 += __shfl_xor_sync(0xffffffffu, s1, 1);
        s1 += __shfl_xor_sync(0xffffffffu, s1, 2);
        float inv0 = 1.f / s0, inv1 = 1.f / s1;

        // ---- GEMM2 (st-outer): O += Phi*Vhi + Phi*Vlo + Plo*Vhi ----
#pragma unroll
        for (int st = 0; st < 8; st++) {
            // repack this k-step's P C-frags -> A-frags (hi/lo split): 8 regs live
            uint32_t ph0, ph1, ph2, ph3, pl0, pl1, pl2, pl3;
            split2(sacc[2*st  ][0] * inv0, sacc[2*st  ][1] * inv0, ph0, pl0);
            split2(sacc[2*st  ][2] * inv1, sacc[2*st  ][3] * inv1, ph1, pl1);
            split2(sacc[2*st+1][0] * inv0, sacc[2*st+1][1] * inv0, ph2, pl2);
            split2(sacc[2*st+1][2] * inv1, sacc[2*st+1][3] * inv1, ph3, pl3);

            uint32_t vb = (uint32_t)lrow * PITCHB + st * 32 + lcolb;
#pragma unroll
            for (int np = 0; np < 8; np++) {
                uint32_t h0, h1, h2, h3, l0, l1, l2, l3;
                ldmx4(h0, h1, h2, h3, smb + VH_OFF + vb + np * (16 * PITCHB));
                ldmx4(l0, l1, l2, l3, smb + VL_OFF + vb + np * (16 * PITCHB));
                mma_bf16(oacc[2*np  ], ph0, ph1, ph2, ph3, h0, h1);
                mma_bf16(oacc[2*np+1], ph0, ph1, ph2, ph3, h2, h3);
                mma_bf16(oacc[2*np  ], ph0, ph1, ph2, ph3, l0, l1);
                mma_bf16(oacc[2*np+1], ph0, ph1, ph2, ph3, l2, l3);
                mma_bf16(oacc[2*np  ], pl0, pl1, pl2, pl3, h0, h1);
                mma_bf16(oacc[2*np+1], pl0, pl1, pl2, pl3, h2, h3);
            }
        }
    }

    // ---- epilogue: fused write + BN partials ----
    float lsum = 0.f, lsq = 0.f;
    float* F = g_fused + base;
#pragma unroll
    for (int nt = 0; nt < 16; nt++) {
        int c = nt * 8 + q * 2;
        float2 u = make_float2(oacc[nt][0], oacc[nt][1]);
        float2 v = make_float2(oacc[nt][2], oacc[nt][3]);
        *reinterpret_cast<float2*>(F + (long)r0 * 128 + c) = u;
        *reinterpret_cast<float2*>(F + (long)(r0 + 8) * 128 + c) = v;
        lsum += u.x + u.y + v.x + v.y;
        lsq  += u.x*u.x + u.y*u.y + v.x*v.x + v.y*v.y;
    }
#pragma unroll
    for (int o = 16; o; o >>= 1) {
        lsum += __shfl_xor_sync(0xffffffffu, lsum, o);
        lsq  += __shfl_xor_sync(0xffffffffu, lsq , o);
    }
    float* red = reinterpret_cast<float*>(smc + 3 * TILEB);
    if (lane == 0) { red[wid] = lsum; red[8 + wid] = lsq; }
    __syncthreads();
    if (t == 0) {
        float s = 0.f, qq = 0.f;
        for (int w2 = 0; w2 < 8; w2++) { s += red[w2]; qq += red[8 + w2]; }
        g_psum[bc] = s; g_psumsq[bc] = qq;
    }
}

// ============================================================
// BN stats + normalize
// ============================================================
__global__ void stats_kernel(const float* __restrict__ gamma, const float* __restrict__ beta)
{
    int c = threadIdx.x;
    if (c < CC) {
        double s = 0.0, q = 0.0;
        for (int b = 0; b < CB; b++) {
            s += (double)g_psum[b * CC + c];
            q += (double)g_psumsq[b * CC + c];
        }
        double nn = (double)CB * (double)CN;
        double mean = s / nn;
        double var = q / nn - mean * mean;
        float a = (float)((double)gamma[c] * rsqrt(var + 1e-5));
        g_scale[c] = a;
        g_shift[c] = beta[c] - (float)mean * a;
    }
}

__global__ void norm_kernel(float* __restrict__ out)
{
    long i4 = (long)blockIdx.x * blockDim.x + threadIdx.x;
    if (i4 < (TOTE / 4)) {
        int c = (int)((i4 >> 12) & 63);
        float a = g_scale[c], sh = g_shift[c];
        float4 f = reinterpret_cast<const float4*>(g_fused)[i4];
        float4 r;
        r.x = fmaxf(0.f, fmaf(f.x, a, sh));
        r.y = fmaxf(0.f, fmaf(f.y, a, sh));
        r.z = fmaxf(0.f, fmaf(f.z, a, sh));
        r.w = fmaxf(0.f, fmaf(f.w, a, sh));
        reinterpret_cast<float4*>(out)[i4] = r;
    }
}

// ============================================================
// Launch
// ============================================================
#define PROJ_SMEM (3*4096*4)

extern "C" void kernel_launch(void* const* d_in, const int* in_sizes, int n_in,
                              void* d_out, int out_size)
{
    const float* x1    = (const float*)d_in[0];
    const float* x2    = (const float*)d_in[1];
    const float* rssi1 = (const float*)d_in[2];
    const float* rssi2 = (const float*)d_in[3];
    const float* qw    = (const float*)d_in[4];
    const float* qb    = (const float*)d_in[5];
    const float* kw    = (const float*)d_in[6];
    const float* kb    = (const float*)d_in[7];
    const float* vw    = (const float*)d_in[8];
    const float* vb    = (const float*)d_in[9];
    const float* gamma = (const float*)d_in[10];
    const float* beta  = (const float*)d_in[11];
    float* out = (float*)d_out;

    cudaFuncSetAttribute(proj_kernel, cudaFuncAttributeMaxDynamicSharedMemorySize, PROJ_SMEM);
    cudaFuncSetAttribute(attn_kernel, cudaFuncAttributeMaxDynamicSharedMemorySize, ATTN_SMEM);

    dim3 pg(CN / 256, CB);
    proj_kernel<<<pg, 256, PROJ_SMEM>>>(x1, rssi1, qw, qb, kw, kb, vw, vb, 0);
    proj_kernel<<<pg, 256, PROJ_SMEM>>>(x2, rssi2, qw, qb, kw, kb, vw, vb, 1);
    vsplit_kernel<<<dim3(CB * CC, 2), 256>>>();
    attn_kernel<<<CB * CC, 256, ATTN_SMEM>>>();
    stats_kernel<<<1, 64>>>(gamma, beta);
    norm_kernel<<<TOTE / 4 / 256, 256>>>(out);
}

// round 11
// speedup vs baseline: 1.9487x; 1.3159x over previous
#include <cuda_runtime.h>
#include <cuda_bf16.h>
#include <cstdint>

// Problem constants
#define CB 16
#define CC 64
#define CH 128
#define CW 128
#define CN (CH*CW)
#define PLANE ((long)CC*CN)
#define TOTE 16777216

// -------- scratch (device globals) --------
__device__ float          g_v[2][TOTE];     // V fp32 (pre-transpose)
__device__ __nv_bfloat16  g_qb[2][TOTE];    // Q bf16 [h,w]
__device__ __nv_bfloat16  g_kb[2][TOTE];    // K bf16 [g,w]
__device__ __nv_bfloat16  g_vth[2][TOTE];   // V^T hi bf16 [w,g]
__device__ __nv_bfloat16  g_vtl[2][TOTE];   // V^T lo bf16 [w,g]
__device__ float          g_fused[TOTE];
__device__ float          g_psum[CB*CC];
__device__ float          g_psumsq[CB*CC];
__device__ float          g_scale[CC];
__device__ float          g_shift[CC];

// ============================================================
// mma.sync / ldmatrix helpers (sm_80 PTX; safe on generic compute_103)
// ============================================================
__device__ __forceinline__ void mma_bf16(float d[4],
                                         uint32_t a0, uint32_t a1, uint32_t a2, uint32_t a3,
                                         uint32_t b0, uint32_t b1)
{
    asm volatile(
        "mma.sync.aligned.m16n8k16.row.col.f32.bf16.bf16.f32 "
        "{%0,%1,%2,%3}, {%4,%5,%6,%7}, {%8,%9}, {%0,%1,%2,%3};"
        : "+f"(d[0]), "+f"(d[1]), "+f"(d[2]), "+f"(d[3])
        : "r"(a0), "r"(a1), "r"(a2), "r"(a3), "r"(b0), "r"(b1));
}

__device__ __forceinline__ void ldmx4(uint32_t& b0, uint32_t& b1, uint32_t& b2, uint32_t& b3,
                                      uint32_t addr)
{
    asm volatile("ldmatrix.sync.aligned.m8n8.x4.shared.b16 {%0,%1,%2,%3}, [%4];"
                 : "=r"(b0), "=r"(b1), "=r"(b2), "=r"(b3) : "r"(addr));
}

__device__ __forceinline__ uint32_t smem_to_u32(const void* p) {
    uint32_t a;
    asm("{ .reg .u64 tmp; cvta.to.shared.u64 tmp, %1; cvt.u32.u64 %0, tmp; }" : "=r"(a) : "l"(p));
    return a;
}

__device__ __forceinline__ uint32_t ld32(const __nv_bfloat16* p) {
    return *reinterpret_cast<const uint32_t*>(p);
}

__device__ __forceinline__ uint32_t packbf(__nv_bfloat16 lo, __nv_bfloat16 hi) {
    return (uint32_t)__bfloat16_as_ushort(lo) | ((uint32_t)__bfloat16_as_ushort(hi) << 16);
}

// split (x,y) into bf16 hi pair + bf16 residual pair
__device__ __forceinline__ void split2(float x, float y, uint32_t& hi, uint32_t& lo) {
    __nv_bfloat16 hx = __float2bfloat16(x), hy = __float2bfloat16(y);
    float rx = x - __bfloat162float(hx);
    float ry = y - __bfloat162float(hy);
    hi = packbf(hx, hy);
    lo = packbf(__float2bfloat16(rx), __float2bfloat16(ry));
}

// ============================================================
// Fused projection via mma.sync (both branches, Q/K bf16, V split-bf16)
// CTA: 256 thr, 1 batch x 256 spatial columns. Tiles staged [n][c] bf16.
// ============================================================
#define WPITCH 144            // 64 bf16 cols + pad (9 x 16B, ldmatrix/LDS conflict-free)
#define XPITCH 144
#define WQ_OFF  0
#define WK_OFF  9216
#define WVH_OFF 18432
#define WVL_OFF 27648
#define XR_OFF  36864
#define XH_OFF  73728
#define XL_OFF  110592
#define PROJ2_SMEM 147456

// A-fragment (weights) from smem W[o][c], row-major, WPITCH bytes/row.
// Verified fragment indexing (R8 pattern): a0=A[m0+t/4][k0+2(t%4)], a1=+8row, a2=+8col, a3=both.
__device__ __forceinline__ void lda(uint32_t a[4], const char* smW, int mt, int ks, int lane) {
    const char* p = smW + (mt * 16 + (lane >> 2)) * WPITCH + ks * 32 + (lane & 3) * 4;
    a[0] = *(const uint32_t*)p;
    a[1] = *(const uint32_t*)(p + 8 * WPITCH);
    a[2] = *(const uint32_t*)(p + 16);
    a[3] = *(const uint32_t*)(p + 8 * WPITCH + 16);
}

__global__ __launch_bounds__(256, 1) void proj_mma_kernel(
    const float* __restrict__ x1, const float* __restrict__ x2,
    const float* __restrict__ rssi1, const float* __restrict__ rssi2,
    const float* __restrict__ qw, const float* __restrict__ qbias,
    const float* __restrict__ kw, const float* __restrict__ kbias,
    const float* __restrict__ vw, const float* __restrict__ vbias)
{
    extern __shared__ char smc[];
    uint32_t smb = smem_to_u32(smc);
    int t = threadIdx.x, lane = t & 31, wid = t >> 5;
    int b = blockIdx.y;
    int n0 = blockIdx.x * 256;
    long pbase = (long)b * PLANE;

    // ---- stage weights once: Wq, Wk bf16; Wv split hi/lo ----
    for (int i = t; i < 1024; i += 256) {          // 1024 float4 per 64x64 matrix
        int o = i >> 4, c4 = i & 15;               // row o, 4-float col group
        char* rowq = smc + WQ_OFF  + o * WPITCH + c4 * 8;
        char* rowk = smc + WK_OFF  + o * WPITCH + c4 * 8;
        char* rvh  = smc + WVH_OFF + o * WPITCH + c4 * 8;
        char* rvl  = smc + WVL_OFF + o * WPITCH + c4 * 8;
        float4 wq = reinterpret_cast<const float4*>(qw)[i];
        float4 wk = reinterpret_cast<const float4*>(kw)[i];
        float4 wv = reinterpret_cast<const float4*>(vw)[i];
        *(uint32_t*)(rowq)     = packbf(__float2bfloat16(wq.x), __float2bfloat16(wq.y));
        *(uint32_t*)(rowq + 4) = packbf(__float2bfloat16(wq.z), __float2bfloat16(wq.w));
        *(uint32_t*)(rowk)     = packbf(__float2bfloat16(wk.x), __float2bfloat16(wk.y));
        *(uint32_t*)(rowk + 4) = packbf(__float2bfloat16(wk.z), __float2bfloat16(wk.w));
        uint32_t h, l;
        split2(wv.x, wv.y, h, l);
        *(uint32_t*)(rvh) = h; *(uint32_t*)(rvl) = l;
        split2(wv.z, wv.w, h, l);
        *(uint32_t*)(rvh + 4) = h; *(uint32_t*)(rvl + 4) = l;
    }

    int lrow  = (lane & 7) + ((lane >> 4) << 3);   // ldmatrix row-within-16 (verified pattern)
    int lcolb = ((lane >> 3) & 1) * 16;

#pragma unroll 1
    for (int br = 0; br < 2; br++) {
        const float* X = br ? x2 : x1;
        const float* R = br ? rssi2 : rssi1;
        __syncthreads();   // weights staged / previous branch tiles consumed

        // ---- stage x -> xh/xl, rssi -> xr (transposed [n][c] bf16) ----
#pragma unroll
        for (int j = 0; j < 4; j++) {
            int c0 = (wid * 4 + j) * 2;            // channel pair
            const float* xr0 = X + pbase + (long)c0 * CN + n0;
            const float* xr1 = X + pbase + (long)(c0 + 1) * CN + n0;
            const float* rr0 = R + pbase + (long)c0 * CN + n0;
            const float* rr1 = R + pbase + (long)(c0 + 1) * CN + n0;
#pragma unroll
            for (int nch = 0; nch < 8; nch++) {
                int n = nch * 32 + lane;
                uint32_t h, l;
                split2(xr0[n], xr1[n], h, l);
                *(uint32_t*)(smc + XH_OFF + n * XPITCH + c0 * 2) = h;
                *(uint32_t*)(smc + XL_OFF + n * XPITCH + c0 * 2) = l;
                *(uint32_t*)(smc + XR_OFF + n * XPITCH + c0 * 2) =
                    packbf(__float2bfloat16(rr0[n]), __float2bfloat16(rr1[n]));
            }
        }
        __syncthreads();

        uint32_t xrb = smb + XR_OFF + (uint32_t)(wid * 32 + lrow) * XPITCH + lcolb;
        uint32_t xhb = smb + XH_OFF + (uint32_t)(wid * 32 + lrow) * XPITCH + lcolb;
        uint32_t xlb = smb + XL_OFF + (uint32_t)(wid * 32 + lrow) * XPITCH + lcolb;
        long nwb = n0 + wid * 32 + (lane & 3) * 2;  // gmem col base for this thread

        // ================= Q pass (B = rssi tile) =================
        {
            uint32_t bb[2][4][4];                   // [nc16][ks][reg]
#pragma unroll
            for (int nc = 0; nc < 2; nc++)
#pragma unroll
                for (int ks = 0; ks < 4; ks++)
                    ldmx4(bb[nc][ks][0], bb[nc][ks][1], bb[nc][ks][2], bb[nc][ks][3],
                          xrb + nc * (16 * XPITCH) + ks * 32);
#pragma unroll
            for (int mt = 0; mt < 4; mt++) {
                uint32_t aa[4][4];
#pragma unroll
                for (int ks = 0; ks < 4; ks++) lda(aa[ks], smc + WQ_OFF, mt, ks, lane);
                int o = mt * 16 + (lane >> 2);
                float bi0 = __ldg(qbias + o), bi1 = __ldg(qbias + o + 8);
                float c[4][4];
#pragma unroll
                for (int nt = 0; nt < 4; nt++) { c[nt][0] = bi0; c[nt][1] = bi0; c[nt][2] = bi1; c[nt][3] = bi1; }
#pragma unroll
                for (int ks = 0; ks < 4; ks++) {
                    mma_bf16(c[0], aa[ks][0], aa[ks][1], aa[ks][2], aa[ks][3], bb[0][ks][0], bb[0][ks][1]);
                    mma_bf16(c[1], aa[ks][0], aa[ks][1], aa[ks][2], aa[ks][3], bb[0][ks][2], bb[0][ks][3]);
                    mma_bf16(c[2], aa[ks][0], aa[ks][1], aa[ks][2], aa[ks][3], bb[1][ks][0], bb[1][ks][1]);
                    mma_bf16(c[3], aa[ks][0], aa[ks][1], aa[ks][2], aa[ks][3], bb[1][ks][2], bb[1][ks][3]);
                }
                __nv_bfloat16* Qo = g_qb[br] + pbase + (long)o * CN;
#pragma unroll
                for (int nt = 0; nt < 4; nt++) {
                    *(uint32_t*)(Qo + nwb + nt * 8)          = packbf(__float2bfloat16(c[nt][0]), __float2bfloat16(c[nt][1]));
                    *(uint32_t*)(Qo + 8 * CN + nwb + nt * 8) = packbf(__float2bfloat16(c[nt][2]), __float2bfloat16(c[nt][3]));
                }
            }
        }

        // ================= K pass (B = xh tile) =================
        {
            uint32_t bb[2][4][4];
#pragma unroll
            for (int nc = 0; nc < 2; nc++)
#pragma unroll
                for (int ks = 0; ks < 4; ks++)
                    ldmx4(bb[nc][ks][0], bb[nc][ks][1], bb[nc][ks][2], bb[nc][ks][3],
                          xhb + nc * (16 * XPITCH) + ks * 32);
#pragma unroll
            for (int mt = 0; mt < 4; mt++) {
                uint32_t aa[4][4];
#pragma unroll
                for (int ks = 0; ks < 4; ks++) lda(aa[ks], smc + WK_OFF, mt, ks, lane);
                int o = mt * 16 + (lane >> 2);
                float bi0 = __ldg(kbias + o), bi1 = __ldg(kbias + o + 8);
                float c[4][4];
#pragma unroll
                for (int nt = 0; nt < 4; nt++) { c[nt][0] = bi0; c[nt][1] = bi0; c[nt][2] = bi1; c[nt][3] = bi1; }
#pragma unroll
                for (int ks = 0; ks < 4; ks++) {
                    mma_bf16(c[0], aa[ks][0], aa[ks][1], aa[ks][2], aa[ks][3], bb[0][ks][0], bb[0][ks][1]);
                    mma_bf16(c[1], aa[ks][0], aa[ks][1], aa[ks][2], aa[ks][3], bb[0][ks][2], bb[0][ks][3]);
                    mma_bf16(c[2], aa[ks][0], aa[ks][1], aa[ks][2], aa[ks][3], bb[1][ks][0], bb[1][ks][1]);
                    mma_bf16(c[3], aa[ks][0], aa[ks][1], aa[ks][2], aa[ks][3], bb[1][ks][2], bb[1][ks][3]);
                }
                __nv_bfloat16* Ko = g_kb[br] + pbase + (long)o * CN;
#pragma unroll
                for (int nt = 0; nt < 4; nt++) {
                    *(uint32_t*)(Ko + nwb + nt * 8)          = packbf(__float2bfloat16(c[nt][0]), __float2bfloat16(c[nt][1]));
                    *(uint32_t*)(Ko + 8 * CN + nwb + nt * 8) = packbf(__float2bfloat16(c[nt][2]), __float2bfloat16(c[nt][3]));
                }
            }
        }

        // ================= V pass (split: Wvh*xh + Wvh*xl + Wvl*xh) =================
        {
            uint32_t bh[2][4][4], bl[2][4][4];
#pragma unroll
            for (int nc = 0; nc < 2; nc++)
#pragma unroll
                for (int ks = 0; ks < 4; ks++) {
                    ldmx4(bh[nc][ks][0], bh[nc][ks][1], bh[nc][ks][2], bh[nc][ks][3],
                          xhb + nc * (16 * XPITCH) + ks * 32);
                    ldmx4(bl[nc][ks][0], bl[nc][ks][1], bl[nc][ks][2], bl[nc][ks][3],
                          xlb + nc * (16 * XPITCH) + ks * 32);
                }
#pragma unroll
            for (int mt = 0; mt < 4; mt++) {
                uint32_t ah[4][4], al[4][4];
#pragma unroll
                for (int ks = 0; ks < 4; ks++) {
                    lda(ah[ks], smc + WVH_OFF, mt, ks, lane);
                    lda(al[ks], smc + WVL_OFF, mt, ks, lane);
                }
                int o = mt * 16 + (lane >> 2);
                float bi0 = __ldg(vbias + o), bi1 = __ldg(vbias + o + 8);
                float c[4][4];
#pragma unroll
                for (int nt = 0; nt < 4; nt++) { c[nt][0] = bi0; c[nt][1] = bi0; c[nt][2] = bi1; c[nt][3] = bi1; }
#pragma unroll
                for (int ks = 0; ks < 4; ks++) {
#pragma unroll
                    for (int nc = 0; nc < 2; nc++) {
                        mma_bf16(c[2*nc  ], ah[ks][0], ah[ks][1], ah[ks][2], ah[ks][3], bh[nc][ks][0], bh[nc][ks][1]);
                        mma_bf16(c[2*nc+1], ah[ks][0], ah[ks][1], ah[ks][2], ah[ks][3], bh[nc][ks][2], bh[nc][ks][3]);
                        mma_bf16(c[2*nc  ], ah[ks][0], ah[ks][1], ah[ks][2], ah[ks][3], bl[nc][ks][0], bl[nc][ks][1]);
                        mma_bf16(c[2*nc+1], ah[ks][0], ah[ks][1], ah[ks][2], ah[ks][3], bl[nc][ks][2], bl[nc][ks][3]);
                        mma_bf16(c[2*nc  ], al[ks][0], al[ks][1], al[ks][2], al[ks][3], bh[nc][ks][0], bh[nc][ks][1]);
                        mma_bf16(c[2*nc+1], al[ks][0], al[ks][1], al[ks][2], al[ks][3], bh[nc][ks][2], bh[nc][ks][3]);
                    }
                }
                float* Vo = g_v[br] + pbase + (long)o * CN;
#pragma unroll
                for (int nt = 0; nt < 4; nt++) {
                    *reinterpret_cast<float2*>(Vo + nwb + nt * 8)          = make_float2(c[nt][0], c[nt][1]);
                    *reinterpret_cast<float2*>(Vo + 8 * CN + nwb + nt * 8) = make_float2(c[nt][2], c[nt][3]);
                }
            }
        }
    }
}

// ============================================================
// V transpose + bf16 split: g_v [g,w] fp32 -> g_vth/g_vtl [w,g] bf16
// ============================================================
__global__ void vsplit_kernel()
{
    __shared__ float T[32][129];
    int bc = blockIdx.x, br = blockIdx.y;
    int t = threadIdx.x;
    const float* V = g_v[br] + (long)bc * CN;
    __nv_bfloat16* Oh = g_vth[br] + (long)bc * CN;
    __nv_bfloat16* Ol = g_vtl[br] + (long)bc * CN;
    int w = t >> 1, half = t & 1;

    for (int s = 0; s < 4; s++) {
        __syncthreads();
#pragma unroll
        for (int i = 0; i < 16; i++) {
            int idx = t + i * 256;
            T[idx >> 7][idx & 127] = V[(s * 32 + (idx >> 7)) * 128 + (idx & 127)];
        }
        __syncthreads();
        uint32_t ph[8], pl[8];
#pragma unroll
        for (int j = 0; j < 8; j++) {
            float v0 = T[half * 16 + 2*j    ][w];
            float v1 = T[half * 16 + 2*j + 1][w];
            __nv_bfloat16 h0 = __float2bfloat16(v0);
            __nv_bfloat16 h1 = __float2bfloat16(v1);
            __nv_bfloat16 l0 = __float2bfloat16(v0 - __bfloat162float(h0));
            __nv_bfloat16 l1 = __float2bfloat16(v1 - __bfloat162float(h1));
            ph[j] = packbf(h0, h1);
            pl[j] = packbf(l0, l1);
        }
        long ob = (long)w * 128 + s * 32 + half * 16;
        reinterpret_cast<uint4*>(Oh + ob)[0] = make_uint4(ph[0], ph[1], ph[2], ph[3]);
        reinterpret_cast<uint4*>(Oh + ob)[1] = make_uint4(ph[4], ph[5], ph[6], ph[7]);
        reinterpret_cast<uint4*>(Ol + ob)[0] = make_uint4(pl[0], pl[1], pl[2], pl[3]);
        reinterpret_cast<uint4*>(Ol + ob)[1] = make_uint4(pl[4], pl[5], pl[6], pl[7]);
    }
}

// ============================================================
// Attention via mma.sync + smem/ldmatrix operands (unchanged, verified R9).
// ============================================================
#define PITCHB 272
#define TILEB (128*PITCHB)
#define K_OFF 0
#define VH_OFF TILEB
#define VL_OFF (2*TILEB)
#define ATTN_SMEM (3*TILEB + 64)

__device__ __forceinline__ void stage_tile(const __nv_bfloat16* __restrict__ g,
                                           char* smem, int off, int t)
{
    const float4* src = reinterpret_cast<const float4*>(g);
#pragma unroll
    for (int i = 0; i < 8; i++) {
        int idx = t + i * 256;
        int row = idx >> 4, seg = idx & 15;
        *reinterpret_cast<float4*>(smem + off + row * PITCHB + seg * 16) = src[idx];
    }
}

__global__ __launch_bounds__(256, 1) void attn_kernel()
{
    extern __shared__ char smc[];
    uint32_t smb = smem_to_u32(smc);
    int t = threadIdx.x, lane = t & 31, wid = t >> 5;
    int q = lane & 3, gid = lane >> 2;
    int bc = blockIdx.x;
    long base = (long)bc * CN;
    const float sc = 0.088388347648318447f;
    int r0 = wid * 16 + gid;

    int lrow  = (lane & 7) + ((lane >> 4) << 3);
    int lcolb = ((lane >> 3) & 1) * 16;

    float oacc[16][4];
#pragma unroll
    for (int nt = 0; nt < 16; nt++)
#pragma unroll
        for (int j = 0; j < 4; j++) oacc[nt][j] = 0.f;

#pragma unroll 1
    for (int br = 0; br < 2; br++) {
        const __nv_bfloat16* Qp = g_qb[br] + base;

        __syncthreads();
        stage_tile(g_kb[br]  + base, smc, K_OFF, t);
        stage_tile(g_vth[br] + base, smc, VH_OFF, t);
        stage_tile(g_vtl[br] + base, smc, VL_OFF, t);
        __syncthreads();

        float sacc[16][4];
#pragma unroll
        for (int nt = 0; nt < 16; nt++)
#pragma unroll
            for (int j = 0; j < 4; j++) sacc[nt][j] = 0.f;

#pragma unroll
        for (int st = 0; st < 8; st++) {
            int c0 = st * 16 + q * 2;
            uint32_t a0 = ld32(Qp + (long)r0 * 128 + c0);
            uint32_t a1 = ld32(Qp + (long)(r0 + 8) * 128 + c0);
            uint32_t a2 = ld32(Qp + (long)r0 * 128 + c0 + 8);
            uint32_t a3 = ld32(Qp + (long)(r0 + 8) * 128 + c0 + 8);
            uint32_t kb = smb + K_OFF + (uint32_t)lrow * PITCHB + st * 32 + lcolb;
#pragma unroll
            for (int np = 0; np < 8; np++) {
                uint32_t b0, b1, b2, b3;
                ldmx4(b0, b1, b2, b3, kb + np * (16 * PITCHB));
                mma_bf16(sacc[2*np  ], a0, a1, a2, a3, b0, b1);
                mma_bf16(sacc[2*np+1], a0, a1, a2, a3, b2, b3);
            }
        }

        float m0 = -1e30f, m1 = -1e30f;
#pragma unroll
        for (int nt = 0; nt < 16; nt++) {
            m0 = fmaxf(m0, fmaxf(sacc[nt][0], sacc[nt][1]));
            m1 = fmaxf(m1, fmaxf(sacc[nt][2], sacc[nt][3]));
        }
        m0 = fmaxf(m0, __shfl_xor_sync(0xffffffffu, m0, 1));
        m0 = fmaxf(m0, __shfl_xor_sync(0xffffffffu, m0, 2));
        m1 = fmaxf(m1, __shfl_xor_sync(0xffffffffu, m1, 1));
        m1 = fmaxf(m1, __shfl_xor_sync(0xffffffffu, m1, 2));

        float s0 = 0.f, s1 = 0.f;
#pragma unroll
        for (int nt = 0; nt < 16; nt++) {
            sacc[nt][0] = __expf((sacc[nt][0] - m0) * sc);
            sacc[nt][1] = __expf((sacc[nt][1] - m0) * sc);
            sacc[nt][2] = __expf((sacc[nt][2] - m1) * sc);
            sacc[nt][3] = __expf((sacc[nt][3] - m1) * sc);
            s0 += sacc[nt][0] + sacc[nt][1];
            s1 += sacc[nt][2] + sacc[nt][3];
        }
        s0 += __shfl_xor_sync(0xffffffffu, s0, 1);
        s0 += __shfl_xor_sync(0xffffffffu, s0, 2);
        s1 += __shfl_xor_sync(0xffffffffu, s1, 1);
        s1 += __shfl_xor_sync(0xffffffffu, s1, 2);
        float inv0 = 1.f / s0, inv1 = 1.f / s1;

#pragma unroll
        for (int st = 0; st < 8; st++) {
            uint32_t ph0, ph1, ph2, ph3, pl0, pl1, pl2, pl3;
            split2(sacc[2*st  ][0] * inv0, sacc[2*st  ][1] * inv0, ph0, pl0);
            split2(sacc[2*st  ][2] * inv1, sacc[2*st  ][3] * inv1, ph1, pl1);
            split2(sacc[2*st+1][0] * inv0, sacc[2*st+1][1] * inv0, ph2, pl2);
            split2(sacc[2*st+1][2] * inv1, sacc[2*st+1][3] * inv1, ph3, pl3);

            uint32_t vb = (uint32_t)lrow * PITCHB + st * 32 + lcolb;
#pragma unroll
            for (int np = 0; np < 8; np++) {
                uint32_t h0, h1, h2, h3, l0, l1, l2, l3;
                ldmx4(h0, h1, h2, h3, smb + VH_OFF + vb + np * (16 * PITCHB));
                ldmx4(l0, l1, l2, l3, smb + VL_OFF + vb + np * (16 * PITCHB));
                mma_bf16(oacc[2*np  ], ph0, ph1, ph2, ph3, h0, h1);
                mma_bf16(oacc[2*np+1], ph0, ph1, ph2, ph3, h2, h3);
                mma_bf16(oacc[2*np  ], ph0, ph1, ph2, ph3, l0, l1);
                mma_bf16(oacc[2*np+1], ph0, ph1, ph2, ph3, l2, l3);
                mma_bf16(oacc[2*np  ], pl0, pl1, pl2, pl3, h0, h1);
                mma_bf16(oacc[2*np+1], pl0, pl1, pl2, pl3, h2, h3);
            }
        }
    }

    float lsum = 0.f, lsq = 0.f;
    float* F = g_fused + base;
#pragma unroll
    for (int nt = 0; nt < 16; nt++) {
        int c = nt * 8 + q * 2;
        float2 u = make_float2(oacc[nt][0], oacc[nt][1]);
        float2 v = make_float2(oacc[nt][2], oacc[nt][3]);
        *reinterpret_cast<float2*>(F + (long)r0 * 128 + c) = u;
        *reinterpret_cast<float2*>(F + (long)(r0 + 8) * 128 + c) = v;
        lsum += u.x + u.y + v.x + v.y;
        lsq  += u.x*u.x + u.y*u.y + v.x*v.x + v.y*v.y;
    }
#pragma unroll
    for (int o = 16; o; o >>= 1) {
        lsum += __shfl_xor_sync(0xffffffffu, lsum, o);
        lsq  += __shfl_xor_sync(0xffffffffu, lsq , o);
    }
    float* red = reinterpret_cast<float*>(smc + 3 * TILEB);
    if (lane == 0) { red[wid] = lsum; red[8 + wid] = lsq; }
    __syncthreads();
    if (t == 0) {
        float s = 0.f, qq = 0.f;
        for (int w2 = 0; w2 < 8; w2++) { s += red[w2]; qq += red[8 + w2]; }
        g_psum[bc] = s; g_psumsq[bc] = qq;
    }
}

// ============================================================
// BN stats + normalize
// ============================================================
__global__ void stats_kernel(const float* __restrict__ gamma, const float* __restrict__ beta)
{
    int c = threadIdx.x;
    if (c < CC) {
        double s = 0.0, q = 0.0;
        for (int b = 0; b < CB; b++) {
            s += (double)g_psum[b * CC + c];
            q += (double)g_psumsq[b * CC + c];
        }
        double nn = (double)CB * (double)CN;
        double mean = s / nn;
        double var = q / nn - mean * mean;
        float a = (float)((double)gamma[c] * rsqrt(var + 1e-5));
        g_scale[c] = a;
        g_shift[c] = beta[c] - (float)mean * a;
    }
}

__global__ void norm_kernel(float* __restrict__ out)
{
    long i4 = (long)blockIdx.x * blockDim.x + threadIdx.x;
    if (i4 < (TOTE / 4)) {
        int c = (int)((i4 >> 12) & 63);
        float a = g_scale[c], sh = g_shift[c];
        float4 f = reinterpret_cast<const float4*>(g_fused)[i4];
        float4 r;
        r.x = fmaxf(0.f, fmaf(f.x, a, sh));
        r.y = fmaxf(0.f, fmaf(f.y, a, sh));
        r.z = fmaxf(0.f, fmaf(f.z, a, sh));
        r.w = fmaxf(0.f, fmaf(f.w, a, sh));
        reinterpret_cast<float4*>(out)[i4] = r;
    }
}

// ============================================================
// Launch
// ============================================================
extern "C" void kernel_launch(void* const* d_in, const int* in_sizes, int n_in,
                              void* d_out, int out_size)
{
    const float* x1    = (const float*)d_in[0];
    const float* x2    = (const float*)d_in[1];
    const float* rssi1 = (const float*)d_in[2];
    const float* rssi2 = (const float*)d_in[3];
    const float* qw    = (const float*)d_in[4];
    const float* qb    = (const float*)d_in[5];
    const float* kw    = (const float*)d_in[6];
    const float* kb    = (const float*)d_in[7];
    const float* vw    = (const float*)d_in[8];
    const float* vb    = (const float*)d_in[9];
    const float* gamma = (const float*)d_in[10];
    const float* beta  = (const float*)d_in[11];
    float* out = (float*)d_out;

    cudaFuncSetAttribute(proj_mma_kernel, cudaFuncAttributeMaxDynamicSharedMemorySize, PROJ2_SMEM);
    cudaFuncSetAttribute(attn_kernel, cudaFuncAttributeMaxDynamicSharedMemorySize, ATTN_SMEM);

    proj_mma_kernel<<<dim3(CN / 256, CB), 256, PROJ2_SMEM>>>(
        x1, x2, rssi1, rssi2, qw, qb, kw, kb, vw, vb);
    vsplit_kernel<<<dim3(CB * CC, 2), 256>>>();
    attn_kernel<<<CB * CC, 256, ATTN_SMEM>>>();
    stats_kernel<<<1, 64>>>(gamma, beta);
    norm_kernel<<<TOTE / 4 / 256, 256>>>(out);
}

// round 12
// speedup vs baseline: 2.9641x; 1.5211x over previous
#include <cuda_runtime.h>
#include <cuda_bf16.h>
#include <cstdint>

// Problem constants
#define CB 16
#define CC 64
#define CH 128
#define CW 128
#define CN (CH*CW)
#define PLANE ((long)CC*CN)
#define TOTE 16777216

// -------- scratch (device globals) --------
__device__ __nv_bfloat16  g_qb[2][TOTE];    // Q bf16 [h,w]
__device__ __nv_bfloat16  g_kb[2][TOTE];    // K bf16 [g,w]
__device__ __nv_bfloat16  g_vh[2][TOTE];    // V hi bf16, natural [g,w]
__device__ __nv_bfloat16  g_vl[2][TOTE];    // V lo bf16, natural [g,w]
__device__ float          g_fused[TOTE];
__device__ float          g_psum[CB*CC];
__device__ float          g_psumsq[CB*CC];
__device__ float          g_scale[CC];
__device__ float          g_shift[CC];

// ============================================================
// mma.sync / ldmatrix helpers (sm_80 PTX; safe on generic compute_103)
// ============================================================
__device__ __forceinline__ void mma_bf16(float d[4],
                                         uint32_t a0, uint32_t a1, uint32_t a2, uint32_t a3,
                                         uint32_t b0, uint32_t b1)
{
    asm volatile(
        "mma.sync.aligned.m16n8k16.row.col.f32.bf16.bf16.f32 "
        "{%0,%1,%2,%3}, {%4,%5,%6,%7}, {%8,%9}, {%0,%1,%2,%3};"
        : "+f"(d[0]), "+f"(d[1]), "+f"(d[2]), "+f"(d[3])
        : "r"(a0), "r"(a1), "r"(a2), "r"(a3), "r"(b0), "r"(b1));
}

__device__ __forceinline__ void ldmx4(uint32_t& b0, uint32_t& b1, uint32_t& b2, uint32_t& b3,
                                      uint32_t addr)
{
    asm volatile("ldmatrix.sync.aligned.m8n8.x4.shared.b16 {%0,%1,%2,%3}, [%4];"
                 : "=r"(b0), "=r"(b1), "=r"(b2), "=r"(b3) : "r"(addr));
}

__device__ __forceinline__ void ldmx4t(uint32_t& b0, uint32_t& b1, uint32_t& b2, uint32_t& b3,
                                       uint32_t addr)
{
    asm volatile("ldmatrix.sync.aligned.m8n8.x4.trans.shared.b16 {%0,%1,%2,%3}, [%4];"
                 : "=r"(b0), "=r"(b1), "=r"(b2), "=r"(b3) : "r"(addr));
}

__device__ __forceinline__ uint32_t smem_to_u32(const void* p) {
    uint32_t a;
    asm("{ .reg .u64 tmp; cvta.to.shared.u64 tmp, %1; cvt.u32.u64 %0, tmp; }" : "=r"(a) : "l"(p));
    return a;
}

__device__ __forceinline__ uint32_t ld32(const __nv_bfloat16* p) {
    return *reinterpret_cast<const uint32_t*>(p);
}

__device__ __forceinline__ uint32_t packbf(__nv_bfloat16 lo, __nv_bfloat16 hi) {
    return (uint32_t)__bfloat16_as_ushort(lo) | ((uint32_t)__bfloat16_as_ushort(hi) << 16);
}

// split (x,y) into bf16 hi pair + bf16 residual pair
__device__ __forceinline__ void split2(float x, float y, uint32_t& hi, uint32_t& lo) {
    __nv_bfloat16 hx = __float2bfloat16(x), hy = __float2bfloat16(y);
    float rx = x - __bfloat162float(hx);
    float ry = y - __bfloat162float(hy);
    hi = packbf(hx, hy);
    lo = packbf(__float2bfloat16(rx), __float2bfloat16(ry));
}

// ============================================================
// Fused projection via mma.sync. 2 tile buffers -> 110.6KB smem, 2 CTA/SM.
// Per branch: stage x->(T0=hi,T1=lo); K pass; V pass (writes vh/vl bf16);
// stage rssi->T0; Q pass.
// ============================================================
#define WPITCH 144            // 64 bf16 cols + pad (9 x 16B, conflict-free)
#define WQ_OFF  0
#define WK_OFF  9216
#define WVH_OFF 18432
#define WVL_OFF 27648
#define T0_OFF  36864
#define T1_OFF  73728
#define PROJ2_SMEM 110592

// A-fragment (weights) from smem W[o][c], row-major, WPITCH bytes/row.
__device__ __forceinline__ void lda(uint32_t a[4], const char* smW, int mt, int ks, int lane) {
    const char* p = smW + (mt * 16 + (lane >> 2)) * WPITCH + ks * 32 + (lane & 3) * 4;
    a[0] = *(const uint32_t*)p;
    a[1] = *(const uint32_t*)(p + 8 * WPITCH);
    a[2] = *(const uint32_t*)(p + 16);
    a[3] = *(const uint32_t*)(p + 8 * WPITCH + 16);
}

__global__ __launch_bounds__(256, 2) void proj_mma_kernel(
    const float* __restrict__ x1, const float* __restrict__ x2,
    const float* __restrict__ rssi1, const float* __restrict__ rssi2,
    const float* __restrict__ qw, const float* __restrict__ qbias,
    const float* __restrict__ kw, const float* __restrict__ kbias,
    const float* __restrict__ vw, const float* __restrict__ vbias)
{
    extern __shared__ char smc[];
    uint32_t smb = smem_to_u32(smc);
    int t = threadIdx.x, lane = t & 31, wid = t >> 5;
    int b = blockIdx.y;
    int n0 = blockIdx.x * 256;
    long pbase = (long)b * PLANE;

    // ---- stage weights once: Wq, Wk bf16; Wv split hi/lo ----
    for (int i = t; i < 1024; i += 256) {          // 1024 float4 per 64x64 matrix
        int o = i >> 4, c4 = i & 15;
        char* rowq = smc + WQ_OFF  + o * WPITCH + c4 * 8;
        char* rowk = smc + WK_OFF  + o * WPITCH + c4 * 8;
        char* rvh  = smc + WVH_OFF + o * WPITCH + c4 * 8;
        char* rvl  = smc + WVL_OFF + o * WPITCH + c4 * 8;
        float4 wq = reinterpret_cast<const float4*>(qw)[i];
        float4 wk = reinterpret_cast<const float4*>(kw)[i];
        float4 wv = reinterpret_cast<const float4*>(vw)[i];
        *(uint32_t*)(rowq)     = packbf(__float2bfloat16(wq.x), __float2bfloat16(wq.y));
        *(uint32_t*)(rowq + 4) = packbf(__float2bfloat16(wq.z), __float2bfloat16(wq.w));
        *(uint32_t*)(rowk)     = packbf(__float2bfloat16(wk.x), __float2bfloat16(wk.y));
        *(uint32_t*)(rowk + 4) = packbf(__float2bfloat16(wk.z), __float2bfloat16(wk.w));
        uint32_t h, l;
        split2(wv.x, wv.y, h, l);
        *(uint32_t*)(rvh) = h; *(uint32_t*)(rvl) = l;
        split2(wv.z, wv.w, h, l);
        *(uint32_t*)(rvh + 4) = h; *(uint32_t*)(rvl + 4) = l;
    }

    int lrow  = (lane & 7) + ((lane >> 4) << 3);
    int lcolb = ((lane >> 3) & 1) * 16;
    uint32_t tb0 = smb + T0_OFF + (uint32_t)(wid * 32 + lrow) * WPITCH + lcolb;
    uint32_t tb1 = smb + T1_OFF + (uint32_t)(wid * 32 + lrow) * WPITCH + lcolb;
    long nwb = n0 + wid * 32 + (lane & 3) * 2;

#pragma unroll 1
    for (int br = 0; br < 2; br++) {
        const float* X = br ? x2 : x1;
        const float* R = br ? rssi2 : rssi1;
        __syncthreads();   // weights staged / previous branch tiles consumed

        // ---- stage x -> T0 (hi), T1 (lo), transposed [n][c] ----
#pragma unroll
        for (int j = 0; j < 4; j++) {
            int c0 = (wid * 4 + j) * 2;
            const float* xr0 = X + pbase + (long)c0 * CN + n0;
            const float* xr1 = X + pbase + (long)(c0 + 1) * CN + n0;
#pragma unroll
            for (int nch = 0; nch < 8; nch++) {
                int n = nch * 32 + lane;
                uint32_t h, l;
                split2(xr0[n], xr1[n], h, l);
                *(uint32_t*)(smc + T0_OFF + n * WPITCH + c0 * 2) = h;
                *(uint32_t*)(smc + T1_OFF + n * WPITCH + c0 * 2) = l;
            }
        }
        __syncthreads();

        // ================= K pass (B = T0 = xh) =================
        {
            uint32_t bb[2][4][4];
#pragma unroll
            for (int nc = 0; nc < 2; nc++)
#pragma unroll
                for (int ks = 0; ks < 4; ks++)
                    ldmx4(bb[nc][ks][0], bb[nc][ks][1], bb[nc][ks][2], bb[nc][ks][3],
                          tb0 + nc * (16 * WPITCH) + ks * 32);
#pragma unroll
            for (int mt = 0; mt < 4; mt++) {
                uint32_t aa[4][4];
#pragma unroll
                for (int ks = 0; ks < 4; ks++) lda(aa[ks], smc + WK_OFF, mt, ks, lane);
                int o = mt * 16 + (lane >> 2);
                float bi0 = __ldg(kbias + o), bi1 = __ldg(kbias + o + 8);
                float c[4][4];
#pragma unroll
                for (int nt = 0; nt < 4; nt++) { c[nt][0] = bi0; c[nt][1] = bi0; c[nt][2] = bi1; c[nt][3] = bi1; }
#pragma unroll
                for (int ks = 0; ks < 4; ks++) {
                    mma_bf16(c[0], aa[ks][0], aa[ks][1], aa[ks][2], aa[ks][3], bb[0][ks][0], bb[0][ks][1]);
                    mma_bf16(c[1], aa[ks][0], aa[ks][1], aa[ks][2], aa[ks][3], bb[0][ks][2], bb[0][ks][3]);
                    mma_bf16(c[2], aa[ks][0], aa[ks][1], aa[ks][2], aa[ks][3], bb[1][ks][0], bb[1][ks][1]);
                    mma_bf16(c[3], aa[ks][0], aa[ks][1], aa[ks][2], aa[ks][3], bb[1][ks][2], bb[1][ks][3]);
                }
                __nv_bfloat16* Ko = g_kb[br] + pbase + (long)o * CN;
#pragma unroll
                for (int nt = 0; nt < 4; nt++) {
                    *(uint32_t*)(Ko + nwb + nt * 8)          = packbf(__float2bfloat16(c[nt][0]), __float2bfloat16(c[nt][1]));
                    *(uint32_t*)(Ko + 8 * CN + nwb + nt * 8) = packbf(__float2bfloat16(c[nt][2]), __float2bfloat16(c[nt][3]));
                }
            }
        }

        // ================= V pass (split: Wvh*xh + Wvh*xl + Wvl*xh) =================
        // Per-nc blocking keeps live registers under the 128-reg / 2-CTA budget.
#pragma unroll 1
        for (int nc = 0; nc < 2; nc++) {
            uint32_t bh[4][4], bl[4][4];
#pragma unroll
            for (int ks = 0; ks < 4; ks++) {
                ldmx4(bh[ks][0], bh[ks][1], bh[ks][2], bh[ks][3], tb0 + nc * (16 * WPITCH) + ks * 32);
                ldmx4(bl[ks][0], bl[ks][1], bl[ks][2], bl[ks][3], tb1 + nc * (16 * WPITCH) + ks * 32);
            }
#pragma unroll
            for (int mt = 0; mt < 4; mt++) {
                int o = mt * 16 + (lane >> 2);
                float bi0 = __ldg(vbias + o), bi1 = __ldg(vbias + o + 8);
                float c[2][4];
#pragma unroll
                for (int nt = 0; nt < 2; nt++) { c[nt][0] = bi0; c[nt][1] = bi0; c[nt][2] = bi1; c[nt][3] = bi1; }
#pragma unroll
                for (int ks = 0; ks < 4; ks++) {
                    uint32_t ah[4], al[4];
                    lda(ah, smc + WVH_OFF, mt, ks, lane);
                    lda(al, smc + WVL_OFF, mt, ks, lane);
                    mma_bf16(c[0], ah[0], ah[1], ah[2], ah[3], bh[ks][0], bh[ks][1]);
                    mma_bf16(c[1], ah[0], ah[1], ah[2], ah[3], bh[ks][2], bh[ks][3]);
                    mma_bf16(c[0], ah[0], ah[1], ah[2], ah[3], bl[ks][0], bl[ks][1]);
                    mma_bf16(c[1], ah[0], ah[1], ah[2], ah[3], bl[ks][2], bl[ks][3]);
                    mma_bf16(c[0], al[0], al[1], al[2], al[3], bh[ks][0], bh[ks][1]);
                    mma_bf16(c[1], al[0], al[1], al[2], al[3], bh[ks][2], bh[ks][3]);
                }
                // write V hi/lo bf16 in natural layout (replaces fp32 + vsplit)
                __nv_bfloat16* Vh = g_vh[br] + pbase + (long)o * CN;
                __nv_bfloat16* Vl = g_vl[br] + pbase + (long)o * CN;
#pragma unroll
                for (int nt = 0; nt < 2; nt++) {
                    long a0 = nwb + nc * 16 + nt * 8;
                    uint32_t h, l;
                    split2(c[nt][0], c[nt][1], h, l);
                    *(uint32_t*)(Vh + a0) = h;  *(uint32_t*)(Vl + a0) = l;
                    split2(c[nt][2], c[nt][3], h, l);
                    *(uint32_t*)(Vh + 8 * CN + a0) = h;  *(uint32_t*)(Vl + 8 * CN + a0) = l;
                }
            }
        }
        __syncthreads();

        // ---- stage rssi -> T0 bf16 ----
#pragma unroll
        for (int j = 0; j < 4; j++) {
            int c0 = (wid * 4 + j) * 2;
            const float* rr0 = R + pbase + (long)c0 * CN + n0;
            const float* rr1 = R + pbase + (long)(c0 + 1) * CN + n0;
#pragma unroll
            for (int nch = 0; nch < 8; nch++) {
                int n = nch * 32 + lane;
                *(uint32_t*)(smc + T0_OFF + n * WPITCH + c0 * 2) =
                    packbf(__float2bfloat16(rr0[n]), __float2bfloat16(rr1[n]));
            }
        }
        __syncthreads();

        // ================= Q pass (B = T0 = rssi) =================
        {
            uint32_t bb[2][4][4];
#pragma unroll
            for (int nc = 0; nc < 2; nc++)
#pragma unroll
                for (int ks = 0; ks < 4; ks++)
                    ldmx4(bb[nc][ks][0], bb[nc][ks][1], bb[nc][ks][2], bb[nc][ks][3],
                          tb0 + nc * (16 * WPITCH) + ks * 32);
#pragma unroll
            for (int mt = 0; mt < 4; mt++) {
                uint32_t aa[4][4];
#pragma unroll
                for (int ks = 0; ks < 4; ks++) lda(aa[ks], smc + WQ_OFF, mt, ks, lane);
                int o = mt * 16 + (lane >> 2);
                float bi0 = __ldg(qbias + o), bi1 = __ldg(qbias + o + 8);
                float c[4][4];
#pragma unroll
                for (int nt = 0; nt < 4; nt++) { c[nt][0] = bi0; c[nt][1] = bi0; c[nt][2] = bi1; c[nt][3] = bi1; }
#pragma unroll
                for (int ks = 0; ks < 4; ks++) {
                    mma_bf16(c[0], aa[ks][0], aa[ks][1], aa[ks][2], aa[ks][3], bb[0][ks][0], bb[0][ks][1]);
                    mma_bf16(c[1], aa[ks][0], aa[ks][1], aa[ks][2], aa[ks][3], bb[0][ks][2], bb[0][ks][3]);
                    mma_bf16(c[2], aa[ks][0], aa[ks][1], aa[ks][2], aa[ks][3], bb[1][ks][0], bb[1][ks][1]);
                    mma_bf16(c[3], aa[ks][0], aa[ks][1], aa[ks][2], aa[ks][3], bb[1][ks][2], bb[1][ks][3]);
                }
                __nv_bfloat16* Qo = g_qb[br] + pbase + (long)o * CN;
#pragma unroll
                for (int nt = 0; nt < 4; nt++) {
                    *(uint32_t*)(Qo + nwb + nt * 8)          = packbf(__float2bfloat16(c[nt][0]), __float2bfloat16(c[nt][1]));
                    *(uint32_t*)(Qo + 8 * CN + nwb + nt * 8) = packbf(__float2bfloat16(c[nt][2]), __float2bfloat16(c[nt][3]));
                }
            }
        }
    }
}

// ============================================================
// Attention via mma.sync; V^T fragments from natural layout via ldmatrix.trans.
// ============================================================
#define PITCHB 272
#define TILEB (128*PITCHB)
#define K_OFF 0
#define VH_OFF TILEB
#define VL_OFF (2*TILEB)
#define ATTN_SMEM (3*TILEB + 64)

__device__ __forceinline__ void stage_tile(const __nv_bfloat16* __restrict__ g,
                                           char* smem, int off, int t)
{
    const float4* src = reinterpret_cast<const float4*>(g);
#pragma unroll
    for (int i = 0; i < 8; i++) {
        int idx = t + i * 256;
        int row = idx >> 4, seg = idx & 15;
        *reinterpret_cast<float4*>(smem + off + row * PITCHB + seg * 16) = src[idx];
    }
}

__global__ __launch_bounds__(256, 1) void attn_kernel()
{
    extern __shared__ char smc[];
    uint32_t smb = smem_to_u32(smc);
    int t = threadIdx.x, lane = t & 31, wid = t >> 5;
    int q = lane & 3, gid = lane >> 2;
    int bc = blockIdx.x;
    long base = (long)bc * CN;
    const float sc = 0.088388347648318447f;
    int r0 = wid * 16 + gid;

    // non-trans (K, GEMM1) lane map
    int lrow  = (lane & 7) + ((lane >> 4) << 3);
    int lcolb = ((lane >> 3) & 1) * 16;
    // trans (V, GEMM2) lane map: m0=(w0-7,g0-7), m1=(w0-7,g8-15), m2=(w8-15,g0-7), m3=...
    int trow  = (lane & 7) + (((lane >> 3) & 1) << 3);
    int tcolb = ((lane >> 4) & 1) * 16;

    float oacc[16][4];
#pragma unroll
    for (int nt = 0; nt < 16; nt++)
#pragma unroll
        for (int j = 0; j < 4; j++) oacc[nt][j] = 0.f;

#pragma unroll 1
    for (int br = 0; br < 2; br++) {
        const __nv_bfloat16* Qp = g_qb[br] + base;

        __syncthreads();
        stage_tile(g_kb[br] + base, smc, K_OFF, t);
        stage_tile(g_vh[br] + base, smc, VH_OFF, t);
        stage_tile(g_vl[br] + base, smc, VL_OFF, t);
        __syncthreads();

        float sacc[16][4];
#pragma unroll
        for (int nt = 0; nt < 16; nt++)
#pragma unroll
            for (int j = 0; j < 4; j++) sacc[nt][j] = 0.f;

#pragma unroll
        for (int st = 0; st < 8; st++) {
            int c0 = st * 16 + q * 2;
            uint32_t a0 = ld32(Qp + (long)r0 * 128 + c0);
            uint32_t a1 = ld32(Qp + (long)(r0 + 8) * 128 + c0);
            uint32_t a2 = ld32(Qp + (long)r0 * 128 + c0 + 8);
            uint32_t a3 = ld32(Qp + (long)(r0 + 8) * 128 + c0 + 8);
            uint32_t kb = smb + K_OFF + (uint32_t)lrow * PITCHB + st * 32 + lcolb;
#pragma unroll
            for (int np = 0; np < 8; np++) {
                uint32_t b0, b1, b2, b3;
                ldmx4(b0, b1, b2, b3, kb + np * (16 * PITCHB));
                mma_bf16(sacc[2*np  ], a0, a1, a2, a3, b0, b1);
                mma_bf16(sacc[2*np+1], a0, a1, a2, a3, b2, b3);
            }
        }

        float m0 = -1e30f, m1 = -1e30f;
#pragma unroll
        for (int nt = 0; nt < 16; nt++) {
            m0 = fmaxf(m0, fmaxf(sacc[nt][0], sacc[nt][1]));
            m1 = fmaxf(m1, fmaxf(sacc[nt][2], sacc[nt][3]));
        }
        m0 = fmaxf(m0, __shfl_xor_sync(0xffffffffu, m0, 1));
        m0 = fmaxf(m0, __shfl_xor_sync(0xffffffffu, m0, 2));
        m1 = fmaxf(m1, __shfl_xor_sync(0xffffffffu, m1, 1));
        m1 = fmaxf(m1, __shfl_xor_sync(0xffffffffu, m1, 2));

        float s0 = 0.f, s1 = 0.f;
#pragma unroll
        for (int nt = 0; nt < 16; nt++) {
            sacc[nt][0] = __expf((sacc[nt][0] - m0) * sc);
            sacc[nt][1] = __expf((sacc[nt][1] - m0) * sc);
            sacc[nt][2] = __expf((sacc[nt][2] - m1) * sc);
            sacc[nt][3] = __expf((sacc[nt][3] - m1) * sc);
            s0 += sacc[nt][0] + sacc[nt][1];
            s1 += sacc[nt][2] + sacc[nt][3];
        }
        s0 += __shfl_xor_sync(0xffffffffu, s0, 1);
        s0 += __shfl_xor_sync(0xffffffffu, s0, 2);
        s1 += __shfl_xor_sync(0xffffffffu, s1, 1);
        s1 += __shfl_xor_sync(0xffffffffu, s1, 2);
        float inv0 = 1.f / s0, inv1 = 1.f / s1;

#pragma unroll
        for (int st = 0; st < 8; st++) {
            uint32_t ph0, ph1, ph2, ph3, pl0, pl1, pl2, pl3;
            split2(sacc[2*st  ][0] * inv0, sacc[2*st  ][1] * inv0, ph0, pl0);
            split2(sacc[2*st  ][2] * inv1, sacc[2*st  ][3] * inv1, ph1, pl1);
            split2(sacc[2*st+1][0] * inv0, sacc[2*st+1][1] * inv0, ph2, pl2);
            split2(sacc[2*st+1][2] * inv1, sacc[2*st+1][3] * inv1, ph3, pl3);

            // V^T fragments: source rows g = st*16 + trow, cols w = np*16 (+tcolb)
            uint32_t vb = (uint32_t)(st * 16 + trow) * PITCHB + tcolb;
#pragma unroll
            for (int np = 0; np < 8; np++) {
                uint32_t h0, h1, h2, h3, l0, l1, l2, l3;
                ldmx4t(h0, h1, h2, h3, smb + VH_OFF + vb + np * 32);
                ldmx4t(l0, l1, l2, l3, smb + VL_OFF + vb + np * 32);
                mma_bf16(oacc[2*np  ], ph0, ph1, ph2, ph3, h0, h1);
                mma_bf16(oacc[2*np+1], ph0, ph1, ph2, ph3, h2, h3);
                mma_bf16(oacc[2*np  ], ph0, ph1, ph2, ph3, l0, l1);
                mma_bf16(oacc[2*np+1], ph0, ph1, ph2, ph3, l2, l3);
                mma_bf16(oacc[2*np  ], pl0, pl1, pl2, pl3, h0, h1);
                mma_bf16(oacc[2*np+1], pl0, pl1, pl2, pl3, h2, h3);
            }
        }
    }

    float lsum = 0.f, lsq = 0.f;
    float* F = g_fused + base;
#pragma unroll
    for (int nt = 0; nt < 16; nt++) {
        int c = nt * 8 + q * 2;
        float2 u = make_float2(oacc[nt][0], oacc[nt][1]);
        float2 v = make_float2(oacc[nt][2], oacc[nt][3]);
        *reinterpret_cast<float2*>(F + (long)r0 * 128 + c) = u;
        *reinterpret_cast<float2*>(F + (long)(r0 + 8) * 128 + c) = v;
        lsum += u.x + u.y + v.x + v.y;
        lsq  += u.x*u.x + u.y*u.y + v.x*v.x + v.y*v.y;
    }
#pragma unroll
    for (int o = 16; o; o >>= 1) {
        lsum += __shfl_xor_sync(0xffffffffu, lsum, o);
        lsq  += __shfl_xor_sync(0xffffffffu, lsq , o);
    }
    float* red = reinterpret_cast<float*>(smc + 3 * TILEB);
    if (lane == 0) { red[wid] = lsum; red[8 + wid] = lsq; }
    __syncthreads();
    if (t == 0) {
        float s = 0.f, qq = 0.f;
        for (int w2 = 0; w2 < 8; w2++) { s += red[w2]; qq += red[8 + w2]; }
        g_psum[bc] = s; g_psumsq[bc] = qq;
    }
}

// ============================================================
// BN stats + normalize
// ============================================================
__global__ void stats_kernel(const float* __restrict__ gamma, const float* __restrict__ beta)
{
    int c = threadIdx.x;
    if (c < CC) {
        double s = 0.0, q = 0.0;
        for (int b = 0; b < CB; b++) {
            s += (double)g_psum[b * CC + c];
            q += (double)g_psumsq[b * CC + c];
        }
        double nn = (double)CB * (double)CN;
        double mean = s / nn;
        double var = q / nn - mean * mean;
        float a = (float)((double)gamma[c] * rsqrt(var + 1e-5));
        g_scale[c] = a;
        g_shift[c] = beta[c] - (float)mean * a;
    }
}

__global__ void norm_kernel(float* __restrict__ out)
{
    long i4 = (long)blockIdx.x * blockDim.x + threadIdx.x;
    if (i4 < (TOTE / 4)) {
        int c = (int)((i4 >> 12) & 63);
        float a = g_scale[c], sh = g_shift[c];
        float4 f = reinterpret_cast<const float4*>(g_fused)[i4];
        float4 r;
        r.x = fmaxf(0.f, fmaf(f.x, a, sh));
        r.y = fmaxf(0.f, fmaf(f.y, a, sh));
        r.z = fmaxf(0.f, fmaf(f.z, a, sh));
        r.w = fmaxf(0.f, fmaf(f.w, a, sh));
        reinterpret_cast<float4*>(out)[i4] = r;
    }
}

// ============================================================
// Launch
// ============================================================
extern "C" void kernel_launch(void* const* d_in, const int* in_sizes, int n_in,
                              void* d_out, int out_size)
{
    const float* x1    = (const float*)d_in[0];
    const float* x2    = (const float*)d_in[1];
    const float* rssi1 = (const float*)d_in[2];
    const float* rssi2 = (const float*)d_in[3];
    const float* qw    = (const float*)d_in[4];
    const float* qb    = (const float*)d_in[5];
    const float* kw    = (const float*)d_in[6];
    const float* kb    = (const float*)d_in[7];
    const float* vw    = (const float*)d_in[8];
    const float* vb    = (const float*)d_in[9];
    const float* gamma = (const float*)d_in[10];
    const float* beta  = (const float*)d_in[11];
    float* out = (float*)d_out;

    cudaFuncSetAttribute(proj_mma_kernel, cudaFuncAttributeMaxDynamicSharedMemorySize, PROJ2_SMEM);
    cudaFuncSetAttribute(attn_kernel, cudaFuncAttributeMaxDynamicSharedMemorySize, ATTN_SMEM);

    proj_mma_kernel<<<dim3(CN / 256, CB), 256, PROJ2_SMEM>>>(
        x1, x2, rssi1, rssi2, qw, qb, kw, kb, vw, vb);
    attn_kernel<<<CB * CC, 256, ATTN_SMEM>>>();
    stats_kernel<<<1, 64>>>(gamma, beta);
    norm_kernel<<<TOTE / 4 / 256, 256>>>(out);
}

// round 13
// speedup vs baseline: 3.2071x; 1.0820x over previous
#include <cuda_runtime.h>
#include <cuda_bf16.h>
#include <cstdint>

// Problem constants
#define CB 16
#define CC 64
#define CH 128
#define CW 128
#define CN (CH*CW)
#define PLANE ((long)CC*CN)
#define TOTE 16777216

// -------- scratch (device globals) --------
__device__ __nv_bfloat16  g_qb[2][TOTE];    // Q bf16 [h,w]
__device__ __nv_bfloat16  g_kb[2][TOTE];    // K bf16 [g,w]
__device__ __nv_bfloat16  g_vh[2][TOTE];    // V hi bf16, natural [g,w]
__device__ __nv_bfloat16  g_vl[2][TOTE];    // V lo bf16, natural [g,w]
__device__ float          g_fused[TOTE];
__device__ float          g_psum[CB*CC];
__device__ float          g_psumsq[CB*CC];
__device__ float          g_scale[CC];
__device__ float          g_shift[CC];

// ============================================================
// mma.sync / ldmatrix helpers (sm_80 PTX; safe on generic compute_103)
// ============================================================
__device__ __forceinline__ void mma_bf16(float d[4],
                                         uint32_t a0, uint32_t a1, uint32_t a2, uint32_t a3,
                                         uint32_t b0, uint32_t b1)
{
    asm volatile(
        "mma.sync.aligned.m16n8k16.row.col.f32.bf16.bf16.f32 "
        "{%0,%1,%2,%3}, {%4,%5,%6,%7}, {%8,%9}, {%0,%1,%2,%3};"
        : "+f"(d[0]), "+f"(d[1]), "+f"(d[2]), "+f"(d[3])
        : "r"(a0), "r"(a1), "r"(a2), "r"(a3), "r"(b0), "r"(b1));
}

__device__ __forceinline__ void ldmx4(uint32_t& b0, uint32_t& b1, uint32_t& b2, uint32_t& b3,
                                      uint32_t addr)
{
    asm volatile("ldmatrix.sync.aligned.m8n8.x4.shared.b16 {%0,%1,%2,%3}, [%4];"
                 : "=r"(b0), "=r"(b1), "=r"(b2), "=r"(b3) : "r"(addr));
}

__device__ __forceinline__ void ldmx4t(uint32_t& b0, uint32_t& b1, uint32_t& b2, uint32_t& b3,
                                       uint32_t addr)
{
    asm volatile("ldmatrix.sync.aligned.m8n8.x4.trans.shared.b16 {%0,%1,%2,%3}, [%4];"
                 : "=r"(b0), "=r"(b1), "=r"(b2), "=r"(b3) : "r"(addr));
}

__device__ __forceinline__ uint32_t smem_to_u32(const void* p) {
    uint32_t a;
    asm("{ .reg .u64 tmp; cvta.to.shared.u64 tmp, %1; cvt.u32.u64 %0, tmp; }" : "=r"(a) : "l"(p));
    return a;
}

__device__ __forceinline__ uint32_t ld32(const __nv_bfloat16* p) {
    return *reinterpret_cast<const uint32_t*>(p);
}

__device__ __forceinline__ uint32_t packbf(__nv_bfloat16 lo, __nv_bfloat16 hi) {
    return (uint32_t)__bfloat16_as_ushort(lo) | ((uint32_t)__bfloat16_as_ushort(hi) << 16);
}

// split (x,y) into bf16 hi pair + bf16 residual pair
__device__ __forceinline__ void split2(float x, float y, uint32_t& hi, uint32_t& lo) {
    __nv_bfloat16 hx = __float2bfloat16(x), hy = __float2bfloat16(y);
    float rx = x - __bfloat162float(hx);
    float ry = y - __bfloat162float(hy);
    hi = packbf(hx, hy);
    lo = packbf(__float2bfloat16(rx), __float2bfloat16(ry));
}

// ============================================================
// Fused projection via mma.sync, coalesced outputs via smem retile.
// CTA: 256 thr, 128 spatial cols. 108.5KB smem -> 2 CTA/SM.
// ============================================================
#define WPITCH 144            // 64 bf16 cols + pad (9 x 16B)
#define OPITCH 272            // 128 bf16 cols + pad (17 x 16B)
#define WQ_OFF  0
#define WK_OFF  9216
#define WVH_OFF 18432
#define WVL_OFF 27648
#define T0_OFF  36864
#define T1_OFF  55296
#define OS0_OFF 73728
#define OS1_OFF 91136
#define PROJ2_SMEM 108544

// A-fragment (weights) from smem W[o][c], row-major, WPITCH bytes/row.
__device__ __forceinline__ void lda(uint32_t a[4], const char* smW, int mt, int ks, int lane) {
    const char* p = smW + (mt * 16 + (lane >> 2)) * WPITCH + ks * 32 + (lane & 3) * 4;
    a[0] = *(const uint32_t*)p;
    a[1] = *(const uint32_t*)(p + 8 * WPITCH);
    a[2] = *(const uint32_t*)(p + 16);
    a[3] = *(const uint32_t*)(p + 8 * WPITCH + 16);
}

__global__ __launch_bounds__(256, 2) void proj_mma_kernel(
    const float* __restrict__ x1, const float* __restrict__ x2,
    const float* __restrict__ rssi1, const float* __restrict__ rssi2,
    const float* __restrict__ qw, const float* __restrict__ qbias,
    const float* __restrict__ kw, const float* __restrict__ kbias,
    const float* __restrict__ vw, const float* __restrict__ vbias)
{
    extern __shared__ char smc[];
    uint32_t smb = smem_to_u32(smc);
    int t = threadIdx.x, lane = t & 31, wid = t >> 5;
    int b = blockIdx.y;
    int n0 = blockIdx.x * 128;
    long pbase = (long)b * PLANE;

    // ---- stage weights once: Wq, Wk bf16; Wv split hi/lo ----
    for (int i = t; i < 1024; i += 256) {
        int o = i >> 4, c4 = i & 15;
        char* rowq = smc + WQ_OFF  + o * WPITCH + c4 * 8;
        char* rowk = smc + WK_OFF  + o * WPITCH + c4 * 8;
        char* rvh  = smc + WVH_OFF + o * WPITCH + c4 * 8;
        char* rvl  = smc + WVL_OFF + o * WPITCH + c4 * 8;
        float4 wq = reinterpret_cast<const float4*>(qw)[i];
        float4 wk = reinterpret_cast<const float4*>(kw)[i];
        float4 wv = reinterpret_cast<const float4*>(vw)[i];
        *(uint32_t*)(rowq)     = packbf(__float2bfloat16(wq.x), __float2bfloat16(wq.y));
        *(uint32_t*)(rowq + 4) = packbf(__float2bfloat16(wq.z), __float2bfloat16(wq.w));
        *(uint32_t*)(rowk)     = packbf(__float2bfloat16(wk.x), __float2bfloat16(wk.y));
        *(uint32_t*)(rowk + 4) = packbf(__float2bfloat16(wk.z), __float2bfloat16(wk.w));
        uint32_t h, l;
        split2(wv.x, wv.y, h, l);
        *(uint32_t*)(rvh) = h; *(uint32_t*)(rvl) = l;
        split2(wv.z, wv.w, h, l);
        *(uint32_t*)(rvh + 4) = h; *(uint32_t*)(rvl + 4) = l;
    }

    int lrow  = (lane & 7) + ((lane >> 4) << 3);
    int lcolb = ((lane >> 3) & 1) * 16;
    uint32_t tb0 = smb + T0_OFF + (uint32_t)(wid * 16 + lrow) * WPITCH + lcolb;
    uint32_t tb1 = smb + T1_OFF + (uint32_t)(wid * 16 + lrow) * WPITCH + lcolb;
    int ncolb = (wid * 16 + (lane & 3) * 2) * 2;   // byte col base in OS tiles

#pragma unroll 1
    for (int br = 0; br < 2; br++) {
        const float* X = br ? x2 : x1;
        const float* R = br ? rssi2 : rssi1;
        __syncthreads();   // weights / previous-branch OS+T consumed

        // ---- stage x -> T0 (hi), T1 (lo), transposed [n][c] ----
#pragma unroll
        for (int j = 0; j < 4; j++) {
            int c0 = (wid * 4 + j) * 2;
            const float* xr0 = X + pbase + (long)c0 * CN + n0;
            const float* xr1 = X + pbase + (long)(c0 + 1) * CN + n0;
#pragma unroll
            for (int nch = 0; nch < 4; nch++) {
                int n = nch * 32 + lane;
                uint32_t h, l;
                split2(xr0[n], xr1[n], h, l);
                *(uint32_t*)(smc + T0_OFF + n * WPITCH + c0 * 2) = h;
                *(uint32_t*)(smc + T1_OFF + n * WPITCH + c0 * 2) = l;
            }
        }
        __syncthreads();

        // ================= K pass (B = T0 = xh) -> OS0 =================
        {
            uint32_t bb[4][4];
#pragma unroll
            for (int ks = 0; ks < 4; ks++)
                ldmx4(bb[ks][0], bb[ks][1], bb[ks][2], bb[ks][3], tb0 + ks * 32);
#pragma unroll
            for (int mt = 0; mt < 4; mt++) {
                int o = mt * 16 + (lane >> 2);
                float bi0 = __ldg(kbias + o), bi1 = __ldg(kbias + o + 8);
                float c[2][4];
#pragma unroll
                for (int nt = 0; nt < 2; nt++) { c[nt][0] = bi0; c[nt][1] = bi0; c[nt][2] = bi1; c[nt][3] = bi1; }
#pragma unroll
                for (int ks = 0; ks < 4; ks++) {
                    uint32_t aa[4];
                    lda(aa, smc + WK_OFF, mt, ks, lane);
                    mma_bf16(c[0], aa[0], aa[1], aa[2], aa[3], bb[ks][0], bb[ks][1]);
                    mma_bf16(c[1], aa[0], aa[1], aa[2], aa[3], bb[ks][2], bb[ks][3]);
                }
#pragma unroll
                for (int nt = 0; nt < 2; nt++) {
                    *(uint32_t*)(smc + OS0_OFF + o * OPITCH + ncolb + nt * 16)
                        = packbf(__float2bfloat16(c[nt][0]), __float2bfloat16(c[nt][1]));
                    *(uint32_t*)(smc + OS0_OFF + (o + 8) * OPITCH + ncolb + nt * 16)
                        = packbf(__float2bfloat16(c[nt][2]), __float2bfloat16(c[nt][3]));
                }
            }
        }
        __syncthreads();
        // ---- K writeout (coalesced) ----
        {
            __nv_bfloat16* Ko = g_kb[br] + pbase;
#pragma unroll
            for (int i = 0; i < 4; i++) {
                int idx = t + i * 256;
                int row = idx >> 4, seg = idx & 15;
                uint4 v = *(const uint4*)(smc + OS0_OFF + row * OPITCH + seg * 16);
                *reinterpret_cast<uint4*>(Ko + (long)row * CN + n0 + seg * 8) = v;
            }
        }
        __syncthreads();

        // ================= V pass (split) -> OS0 (hi), OS1 (lo) =================
        {
            uint32_t bh[4][4], bl[4][4];
#pragma unroll
            for (int ks = 0; ks < 4; ks++) {
                ldmx4(bh[ks][0], bh[ks][1], bh[ks][2], bh[ks][3], tb0 + ks * 32);
                ldmx4(bl[ks][0], bl[ks][1], bl[ks][2], bl[ks][3], tb1 + ks * 32);
            }
#pragma unroll
            for (int mt = 0; mt < 4; mt++) {
                int o = mt * 16 + (lane >> 2);
                float bi0 = __ldg(vbias + o), bi1 = __ldg(vbias + o + 8);
                float c[2][4];
#pragma unroll
                for (int nt = 0; nt < 2; nt++) { c[nt][0] = bi0; c[nt][1] = bi0; c[nt][2] = bi1; c[nt][3] = bi1; }
#pragma unroll
                for (int ks = 0; ks < 4; ks++) {
                    uint32_t ah[4], al[4];
                    lda(ah, smc + WVH_OFF, mt, ks, lane);
                    lda(al, smc + WVL_OFF, mt, ks, lane);
                    mma_bf16(c[0], ah[0], ah[1], ah[2], ah[3], bh[ks][0], bh[ks][1]);
                    mma_bf16(c[1], ah[0], ah[1], ah[2], ah[3], bh[ks][2], bh[ks][3]);
                    mma_bf16(c[0], ah[0], ah[1], ah[2], ah[3], bl[ks][0], bl[ks][1]);
                    mma_bf16(c[1], ah[0], ah[1], ah[2], ah[3], bl[ks][2], bl[ks][3]);
                    mma_bf16(c[0], al[0], al[1], al[2], al[3], bh[ks][0], bh[ks][1]);
                    mma_bf16(c[1], al[0], al[1], al[2], al[3], bh[ks][2], bh[ks][3]);
                }
#pragma unroll
                for (int nt = 0; nt < 2; nt++) {
                    uint32_t h, l;
                    split2(c[nt][0], c[nt][1], h, l);
                    *(uint32_t*)(smc + OS0_OFF + o * OPITCH + ncolb + nt * 16) = h;
                    *(uint32_t*)(smc + OS1_OFF + o * OPITCH + ncolb + nt * 16) = l;
                    split2(c[nt][2], c[nt][3], h, l);
                    *(uint32_t*)(smc + OS0_OFF + (o + 8) * OPITCH + ncolb + nt * 16) = h;
                    *(uint32_t*)(smc + OS1_OFF + (o + 8) * OPITCH + ncolb + nt * 16) = l;
                }
            }
        }
        __syncthreads();
        // ---- V writeout (coalesced) + stage rssi -> T0 ----
        {
            __nv_bfloat16* Vh = g_vh[br] + pbase;
            __nv_bfloat16* Vl = g_vl[br] + pbase;
#pragma unroll
            for (int i = 0; i < 4; i++) {
                int idx = t + i * 256;
                int row = idx >> 4, seg = idx & 15;
                uint4 vh = *(const uint4*)(smc + OS0_OFF + row * OPITCH + seg * 16);
                uint4 vl = *(const uint4*)(smc + OS1_OFF + row * OPITCH + seg * 16);
                *reinterpret_cast<uint4*>(Vh + (long)row * CN + n0 + seg * 8) = vh;
                *reinterpret_cast<uint4*>(Vl + (long)row * CN + n0 + seg * 8) = vl;
            }
#pragma unroll
            for (int j = 0; j < 4; j++) {
                int c0 = (wid * 4 + j) * 2;
                const float* rr0 = R + pbase + (long)c0 * CN + n0;
                const float* rr1 = R + pbase + (long)(c0 + 1) * CN + n0;
#pragma unroll
                for (int nch = 0; nch < 4; nch++) {
                    int n = nch * 32 + lane;
                    *(uint32_t*)(smc + T0_OFF + n * WPITCH + c0 * 2) =
                        packbf(__float2bfloat16(rr0[n]), __float2bfloat16(rr1[n]));
                }
            }
        }
        __syncthreads();

        // ================= Q pass (B = T0 = rssi) -> OS0 =================
        {
            uint32_t bb[4][4];
#pragma unroll
            for (int ks = 0; ks < 4; ks++)
                ldmx4(bb[ks][0], bb[ks][1], bb[ks][2], bb[ks][3], tb0 + ks * 32);
#pragma unroll
            for (int mt = 0; mt < 4; mt++) {
                int o = mt * 16 + (lane >> 2);
                float bi0 = __ldg(qbias + o), bi1 = __ldg(qbias + o + 8);
                float c[2][4];
#pragma unroll
                for (int nt = 0; nt < 2; nt++) { c[nt][0] = bi0; c[nt][1] = bi0; c[nt][2] = bi1; c[nt][3] = bi1; }
#pragma unroll
                for (int ks = 0; ks < 4; ks++) {
                    uint32_t aa[4];
                    lda(aa, smc + WQ_OFF, mt, ks, lane);
                    mma_bf16(c[0], aa[0], aa[1], aa[2], aa[3], bb[ks][0], bb[ks][1]);
                    mma_bf16(c[1], aa[0], aa[1], aa[2], aa[3], bb[ks][2], bb[ks][3]);
                }
#pragma unroll
                for (int nt = 0; nt < 2; nt++) {
                    *(uint32_t*)(smc + OS0_OFF + o * OPITCH + ncolb + nt * 16)
                        = packbf(__float2bfloat16(c[nt][0]), __float2bfloat16(c[nt][1]));
                    *(uint32_t*)(smc + OS0_OFF + (o + 8) * OPITCH + ncolb + nt * 16)
                        = packbf(__float2bfloat16(c[nt][2]), __float2bfloat16(c[nt][3]));
                }
            }
        }
        __syncthreads();
        // ---- Q writeout (coalesced) ----
        {
            __nv_bfloat16* Qo = g_qb[br] + pbase;
#pragma unroll
            for (int i = 0; i < 4; i++) {
                int idx = t + i * 256;
                int row = idx >> 4, seg = idx & 15;
                uint4 v = *(const uint4*)(smc + OS0_OFF + row * OPITCH + seg * 16);
                *reinterpret_cast<uint4*>(Qo + (long)row * CN + n0 + seg * 8) = v;
            }
        }
    }
}

// ============================================================
// Attention via mma.sync (unchanged, verified R12).
// ============================================================
#define PITCHB 272
#define TILEB (128*PITCHB)
#define K_OFF 0
#define VH_OFF TILEB
#define VL_OFF (2*TILEB)
#define ATTN_SMEM (3*TILEB + 64)

__device__ __forceinline__ void stage_tile(const __nv_bfloat16* __restrict__ g,
                                           char* smem, int off, int t)
{
    const float4* src = reinterpret_cast<const float4*>(g);
#pragma unroll
    for (int i = 0; i < 8; i++) {
        int idx = t + i * 256;
        int row = idx >> 4, seg = idx & 15;
        *reinterpret_cast<float4*>(smem + off + row * PITCHB + seg * 16) = src[idx];
    }
}

__global__ __launch_bounds__(256, 1) void attn_kernel()
{
    extern __shared__ char smc[];
    uint32_t smb = smem_to_u32(smc);
    int t = threadIdx.x, lane = t & 31, wid = t >> 5;
    int q = lane & 3, gid = lane >> 2;
    int bc = blockIdx.x;
    long base = (long)bc * CN;
    const float sc = 0.088388347648318447f;
    int r0 = wid * 16 + gid;

    int lrow  = (lane & 7) + ((lane >> 4) << 3);
    int lcolb = ((lane >> 3) & 1) * 16;
    int trow  = (lane & 7) + (((lane >> 3) & 1) << 3);
    int tcolb = ((lane >> 4) & 1) * 16;

    float oacc[16][4];
#pragma unroll
    for (int nt = 0; nt < 16; nt++)
#pragma unroll
        for (int j = 0; j < 4; j++) oacc[nt][j] = 0.f;

#pragma unroll 1
    for (int br = 0; br < 2; br++) {
        const __nv_bfloat16* Qp = g_qb[br] + base;

        __syncthreads();
        stage_tile(g_kb[br] + base, smc, K_OFF, t);
        stage_tile(g_vh[br] + base, smc, VH_OFF, t);
        stage_tile(g_vl[br] + base, smc, VL_OFF, t);
        __syncthreads();

        float sacc[16][4];
#pragma unroll
        for (int nt = 0; nt < 16; nt++)
#pragma unroll
            for (int j = 0; j < 4; j++) sacc[nt][j] = 0.f;

#pragma unroll
        for (int st = 0; st < 8; st++) {
            int c0 = st * 16 + q * 2;
            uint32_t a0 = ld32(Qp + (long)r0 * 128 + c0);
            uint32_t a1 = ld32(Qp + (long)(r0 + 8) * 128 + c0);
            uint32_t a2 = ld32(Qp + (long)r0 * 128 + c0 + 8);
            uint32_t a3 = ld32(Qp + (long)(r0 + 8) * 128 + c0 + 8);
            uint32_t kb = smb + K_OFF + (uint32_t)lrow * PITCHB + st * 32 + lcolb;
#pragma unroll
            for (int np = 0; np < 8; np++) {
                uint32_t b0, b1, b2, b3;
                ldmx4(b0, b1, b2, b3, kb + np * (16 * PITCHB));
                mma_bf16(sacc[2*np  ], a0, a1, a2, a3, b0, b1);
                mma_bf16(sacc[2*np+1], a0, a1, a2, a3, b2, b3);
            }
        }

        float m0 = -1e30f, m1 = -1e30f;
#pragma unroll
        for (int nt = 0; nt < 16; nt++) {
            m0 = fmaxf(m0, fmaxf(sacc[nt][0], sacc[nt][1]));
            m1 = fmaxf(m1, fmaxf(sacc[nt][2], sacc[nt][3]));
        }
        m0 = fmaxf(m0, __shfl_xor_sync(0xffffffffu, m0, 1));
        m0 = fmaxf(m0, __shfl_xor_sync(0xffffffffu, m0, 2));
        m1 = fmaxf(m1, __shfl_xor_sync(0xffffffffu, m1, 1));
        m1 = fmaxf(m1, __shfl_xor_sync(0xffffffffu, m1, 2));

        float s0 = 0.f, s1 = 0.f;
#pragma unroll
        for (int nt = 0; nt < 16; nt++) {
            sacc[nt][0] = __expf((sacc[nt][0] - m0) * sc);
            sacc[nt][1] = __expf((sacc[nt][1] - m0) * sc);
            sacc[nt][2] = __expf((sacc[nt][2] - m1) * sc);
            sacc[nt][3] = __expf((sacc[nt][3] - m1) * sc);
            s0 += sacc[nt][0] + sacc[nt][1];
            s1 += sacc[nt][2] + sacc[nt][3];
        }
        s0 += __shfl_xor_sync(0xffffffffu, s0, 1);
        s0 += __shfl_xor_sync(0xffffffffu, s0, 2);
        s1 += __shfl_xor_sync(0xffffffffu, s1, 1);
        s1 += __shfl_xor_sync(0xffffffffu, s1, 2);
        float inv0 = 1.f / s0, inv1 = 1.f / s1;

#pragma unroll
        for (int st = 0; st < 8; st++) {
            uint32_t ph0, ph1, ph2, ph3, pl0, pl1, pl2, pl3;
            split2(sacc[2*st  ][0] * inv0, sacc[2*st  ][1] * inv0, ph0, pl0);
            split2(sacc[2*st  ][2] * inv1, sacc[2*st  ][3] * inv1, ph1, pl1);
            split2(sacc[2*st+1][0] * inv0, sacc[2*st+1][1] * inv0, ph2, pl2);
            split2(sacc[2*st+1][2] * inv1, sacc[2*st+1][3] * inv1, ph3, pl3);

            uint32_t vb = (uint32_t)(st * 16 + trow) * PITCHB + tcolb;
#pragma unroll
            for (int np = 0; np < 8; np++) {
                uint32_t h0, h1, h2, h3, l0, l1, l2, l3;
                ldmx4t(h0, h1, h2, h3, smb + VH_OFF + vb + np * 32);
                ldmx4t(l0, l1, l2, l3, smb + VL_OFF + vb + np * 32);
                mma_bf16(oacc[2*np  ], ph0, ph1, ph2, ph3, h0, h1);
                mma_bf16(oacc[2*np+1], ph0, ph1, ph2, ph3, h2, h3);
                mma_bf16(oacc[2*np  ], ph0, ph1, ph2, ph3, l0, l1);
                mma_bf16(oacc[2*np+1], ph0, ph1, ph2, ph3, l2, l3);
                mma_bf16(oacc[2*np  ], pl0, pl1, pl2, pl3, h0, h1);
                mma_bf16(oacc[2*np+1], pl0, pl1, pl2, pl3, h2, h3);
            }
        }
    }

    float lsum = 0.f, lsq = 0.f;
    float* F = g_fused + base;
#pragma unroll
    for (int nt = 0; nt < 16; nt++) {
        int c = nt * 8 + q * 2;
        float2 u = make_float2(oacc[nt][0], oacc[nt][1]);
        float2 v = make_float2(oacc[nt][2], oacc[nt][3]);
        *reinterpret_cast<float2*>(F + (long)r0 * 128 + c) = u;
        *reinterpret_cast<float2*>(F + (long)(r0 + 8) * 128 + c) = v;
        lsum += u.x + u.y + v.x + v.y;
        lsq  += u.x*u.x + u.y*u.y + v.x*v.x + v.y*v.y;
    }
#pragma unroll
    for (int o = 16; o; o >>= 1) {
        lsum += __shfl_xor_sync(0xffffffffu, lsum, o);
        lsq  += __shfl_xor_sync(0xffffffffu, lsq , o);
    }
    float* red = reinterpret_cast<float*>(smc + 3 * TILEB);
    if (lane == 0) { red[wid] = lsum; red[8 + wid] = lsq; }
    __syncthreads();
    if (t == 0) {
        float s = 0.f, qq = 0.f;
        for (int w2 = 0; w2 < 8; w2++) { s += red[w2]; qq += red[8 + w2]; }
        g_psum[bc] = s; g_psumsq[bc] = qq;
    }
}

// ============================================================
// BN stats + normalize
// ============================================================
__global__ void stats_kernel(const float* __restrict__ gamma, const float* __restrict__ beta)
{
    int c = threadIdx.x;
    if (c < CC) {
        double s = 0.0, q = 0.0;
        for (int b = 0; b < CB; b++) {
            s += (double)g_psum[b * CC + c];
            q += (double)g_psumsq[b * CC + c];
        }
        double nn = (double)CB * (double)CN;
        double mean = s / nn;
        double var = q / nn - mean * mean;
        float a = (float)((double)gamma[c] * rsqrt(var + 1e-5));
        g_scale[c] = a;
        g_shift[c] = beta[c] - (float)mean * a;
    }
}

__global__ void norm_kernel(float* __restrict__ out)
{
    long i4 = (long)blockIdx.x * blockDim.x + threadIdx.x;
    if (i4 < (TOTE / 4)) {
        int c = (int)((i4 >> 12) & 63);
        float a = g_scale[c], sh = g_shift[c];
        float4 f = reinterpret_cast<const float4*>(g_fused)[i4];
        float4 r;
        r.x = fmaxf(0.f, fmaf(f.x, a, sh));
        r.y = fmaxf(0.f, fmaf(f.y, a, sh));
        r.z = fmaxf(0.f, fmaf(f.z, a, sh));
        r.w = fmaxf(0.f, fmaf(f.w, a, sh));
        reinterpret_cast<float4*>(out)[i4] = r;
    }
}

// ============================================================
// Launch
// ============================================================
extern "C" void kernel_launch(void* const* d_in, const int* in_sizes, int n_in,
                              void* d_out, int out_size)
{
    const float* x1    = (const float*)d_in[0];
    const float* x2    = (const float*)d_in[1];
    const float* rssi1 = (const float*)d_in[2];
    const float* rssi2 = (const float*)d_in[3];
    const float* qw    = (const float*)d_in[4];
    const float* qb    = (const float*)d_in[5];
    const float* kw    = (const float*)d_in[6];
    const float* kb    = (const float*)d_in[7];
    const float* vw    = (const float*)d_in[8];
    const float* vb    = (const float*)d_in[9];
    const float* gamma = (const float*)d_in[10];
    const float* beta  = (const float*)d_in[11];
    float* out = (float*)d_out;

    cudaFuncSetAttribute(proj_mma_kernel, cudaFuncAttributeMaxDynamicSharedMemorySize, PROJ2_SMEM);
    cudaFuncSetAttribute(attn_kernel, cudaFuncAttributeMaxDynamicSharedMemorySize, ATTN_SMEM);

    proj_mma_kernel<<<dim3(CN / 128, CB), 256, PROJ2_SMEM>>>(
        x1, x2, rssi1, rssi2, qw, qb, kw, kb, vw, vb);
    attn_kernel<<<CB * CC, 256, ATTN_SMEM>>>();
    stats_kernel<<<1, 64>>>(gamma, beta);
    norm_kernel<<<TOTE / 4 / 256, 256>>>(out);
}

// round 14
// speedup vs baseline: 4.1578x; 1.2964x over previous
#include <cuda_runtime.h>
#include <cuda_bf16.h>
#include <cuda_fp16.h>
#include <cstdint>

// Problem constants
#define CB 16
#define CC 64
#define CH 128
#define CW 128
#define CN (CH*CW)
#define PLANE ((long)CC*CN)
#define TOTE 16777216

// -------- scratch (device globals) --------
__device__ __nv_bfloat16  g_qb[2][TOTE];    // Q bf16 [h,w]
__device__ __nv_bfloat16  g_kb[2][TOTE];    // K bf16 [g,w]
__device__ __half         g_vf[2][TOTE];    // V fp16, natural [g,w]
__device__ float          g_fused[TOTE];
__device__ float          g_psum[CB*CC];
__device__ float          g_psumsq[CB*CC];
__device__ float          g_scale[CC];
__device__ float          g_shift[CC];

// ============================================================
// mma.sync / ldmatrix helpers (sm_80 PTX; safe on generic compute_103)
// ============================================================
__device__ __forceinline__ void mma_bf16(float d[4],
                                         uint32_t a0, uint32_t a1, uint32_t a2, uint32_t a3,
                                         uint32_t b0, uint32_t b1)
{
    asm volatile(
        "mma.sync.aligned.m16n8k16.row.col.f32.bf16.bf16.f32 "
        "{%0,%1,%2,%3}, {%4,%5,%6,%7}, {%8,%9}, {%0,%1,%2,%3};"
        : "+f"(d[0]), "+f"(d[1]), "+f"(d[2]), "+f"(d[3])
        : "r"(a0), "r"(a1), "r"(a2), "r"(a3), "r"(b0), "r"(b1));
}

__device__ __forceinline__ void mma_f16h(float d[4],
                                         uint32_t a0, uint32_t a1, uint32_t a2, uint32_t a3,
                                         uint32_t b0, uint32_t b1)
{
    asm volatile(
        "mma.sync.aligned.m16n8k16.row.col.f32.f16.f16.f32 "
        "{%0,%1,%2,%3}, {%4,%5,%6,%7}, {%8,%9}, {%0,%1,%2,%3};"
        : "+f"(d[0]), "+f"(d[1]), "+f"(d[2]), "+f"(d[3])
        : "r"(a0), "r"(a1), "r"(a2), "r"(a3), "r"(b0), "r"(b1));
}

__device__ __forceinline__ void ldmx4(uint32_t& b0, uint32_t& b1, uint32_t& b2, uint32_t& b3,
                                      uint32_t addr)
{
    asm volatile("ldmatrix.sync.aligned.m8n8.x4.shared.b16 {%0,%1,%2,%3}, [%4];"
                 : "=r"(b0), "=r"(b1), "=r"(b2), "=r"(b3) : "r"(addr));
}

__device__ __forceinline__ void ldmx4t(uint32_t& b0, uint32_t& b1, uint32_t& b2, uint32_t& b3,
                                       uint32_t addr)
{
    asm volatile("ldmatrix.sync.aligned.m8n8.x4.trans.shared.b16 {%0,%1,%2,%3}, [%4];"
                 : "=r"(b0), "=r"(b1), "=r"(b2), "=r"(b3) : "r"(addr));
}

__device__ __forceinline__ uint32_t smem_to_u32(const void* p) {
    uint32_t a;
    asm("{ .reg .u64 tmp; cvta.to.shared.u64 tmp, %1; cvt.u32.u64 %0, tmp; }" : "=r"(a) : "l"(p));
    return a;
}

__device__ __forceinline__ uint32_t ld32(const __nv_bfloat16* p) {
    return *reinterpret_cast<const uint32_t*>(p);
}

__device__ __forceinline__ uint32_t packbf(__nv_bfloat16 lo, __nv_bfloat16 hi) {
    return (uint32_t)__bfloat16_as_ushort(lo) | ((uint32_t)__bfloat16_as_ushort(hi) << 16);
}

__device__ __forceinline__ uint32_t packf16(float x, float y) {
    __half2 h = __float22half2_rn(make_float2(x, y));   // x -> low 16 bits
    return *reinterpret_cast<uint32_t*>(&h);
}

// split (x,y) into bf16 hi pair + bf16 residual pair
__device__ __forceinline__ void split2(float x, float y, uint32_t& hi, uint32_t& lo) {
    __nv_bfloat16 hx = __float2bfloat16(x), hy = __float2bfloat16(y);
    float rx = x - __bfloat162float(hx);
    float ry = y - __bfloat162float(hy);
    hi = packbf(hx, hy);
    lo = packbf(__float2bfloat16(rx), __float2bfloat16(ry));
}

// ============================================================
// Fused projection via mma.sync, coalesced outputs via smem retile.
// CTA: 256 thr, 128 spatial cols. 91KB smem -> 2 CTA/SM.
// Q,K out bf16; V out fp16 (compute split-bf16, store fp16).
// ============================================================
#define WPITCH 144            // 64 bf16 cols + pad (9 x 16B)
#define OPITCH 272            // 128 bf16 cols + pad (17 x 16B)
#define WQ_OFF  0
#define WK_OFF  9216
#define WVH_OFF 18432
#define WVL_OFF 27648
#define T0_OFF  36864
#define T1_OFF  55296
#define OS0_OFF 73728
#define PROJ2_SMEM 91136

// A-fragment (weights) from smem W[o][c], row-major, WPITCH bytes/row.
__device__ __forceinline__ void lda(uint32_t a[4], const char* smW, int mt, int ks, int lane) {
    const char* p = smW + (mt * 16 + (lane >> 2)) * WPITCH + ks * 32 + (lane & 3) * 4;
    a[0] = *(const uint32_t*)p;
    a[1] = *(const uint32_t*)(p + 8 * WPITCH);
    a[2] = *(const uint32_t*)(p + 16);
    a[3] = *(const uint32_t*)(p + 8 * WPITCH + 16);
}

__global__ __launch_bounds__(256, 2) void proj_mma_kernel(
    const float* __restrict__ x1, const float* __restrict__ x2,
    const float* __restrict__ rssi1, const float* __restrict__ rssi2,
    const float* __restrict__ qw, const float* __restrict__ qbias,
    const float* __restrict__ kw, const float* __restrict__ kbias,
    const float* __restrict__ vw, const float* __restrict__ vbias)
{
    extern __shared__ char smc[];
    uint32_t smb = smem_to_u32(smc);
    int t = threadIdx.x, lane = t & 31, wid = t >> 5;
    int b = blockIdx.y;
    int n0 = blockIdx.x * 128;
    long pbase = (long)b * PLANE;

    // ---- stage weights once: Wq, Wk bf16; Wv split hi/lo ----
    for (int i = t; i < 1024; i += 256) {
        int o = i >> 4, c4 = i & 15;
        char* rowq = smc + WQ_OFF  + o * WPITCH + c4 * 8;
        char* rowk = smc + WK_OFF  + o * WPITCH + c4 * 8;
        char* rvh  = smc + WVH_OFF + o * WPITCH + c4 * 8;
        char* rvl  = smc + WVL_OFF + o * WPITCH + c4 * 8;
        float4 wq = reinterpret_cast<const float4*>(qw)[i];
        float4 wk = reinterpret_cast<const float4*>(kw)[i];
        float4 wv = reinterpret_cast<const float4*>(vw)[i];
        *(uint32_t*)(rowq)     = packbf(__float2bfloat16(wq.x), __float2bfloat16(wq.y));
        *(uint32_t*)(rowq + 4) = packbf(__float2bfloat16(wq.z), __float2bfloat16(wq.w));
        *(uint32_t*)(rowk)     = packbf(__float2bfloat16(wk.x), __float2bfloat16(wk.y));
        *(uint32_t*)(rowk + 4) = packbf(__float2bfloat16(wk.z), __float2bfloat16(wk.w));
        uint32_t h, l;
        split2(wv.x, wv.y, h, l);
        *(uint32_t*)(rvh) = h; *(uint32_t*)(rvl) = l;
        split2(wv.z, wv.w, h, l);
        *(uint32_t*)(rvh + 4) = h; *(uint32_t*)(rvl + 4) = l;
    }

    int lrow  = (lane & 7) + ((lane >> 4) << 3);
    int lcolb = ((lane >> 3) & 1) * 16;
    uint32_t tb0 = smb + T0_OFF + (uint32_t)(wid * 16 + lrow) * WPITCH + lcolb;
    uint32_t tb1 = smb + T1_OFF + (uint32_t)(wid * 16 + lrow) * WPITCH + lcolb;
    int ncolb = (wid * 16 + (lane & 3) * 2) * 2;   // byte col base in OS tile

#pragma unroll 1
    for (int br = 0; br < 2; br++) {
        const float* X = br ? x2 : x1;
        const float* R = br ? rssi2 : rssi1;
        __syncthreads();   // weights / previous-branch OS+T consumed

        // ---- stage x -> T0 (hi), T1 (lo), transposed [n][c] ----
#pragma unroll
        for (int j = 0; j < 4; j++) {
            int c0 = (wid * 4 + j) * 2;
            const float* xr0 = X + pbase + (long)c0 * CN + n0;
            const float* xr1 = X + pbase + (long)(c0 + 1) * CN + n0;
#pragma unroll
            for (int nch = 0; nch < 4; nch++) {
                int n = nch * 32 + lane;
                uint32_t h, l;
                split2(xr0[n], xr1[n], h, l);
                *(uint32_t*)(smc + T0_OFF + n * WPITCH + c0 * 2) = h;
                *(uint32_t*)(smc + T1_OFF + n * WPITCH + c0 * 2) = l;
            }
        }
        __syncthreads();

        // ================= K pass (B = T0 = xh) -> OS0 =================
        {
            uint32_t bb[4][4];
#pragma unroll
            for (int ks = 0; ks < 4; ks++)
                ldmx4(bb[ks][0], bb[ks][1], bb[ks][2], bb[ks][3], tb0 + ks * 32);
#pragma unroll
            for (int mt = 0; mt < 4; mt++) {
                int o = mt * 16 + (lane >> 2);
                float bi0 = __ldg(kbias + o), bi1 = __ldg(kbias + o + 8);
                float c[2][4];
#pragma unroll
                for (int nt = 0; nt < 2; nt++) { c[nt][0] = bi0; c[nt][1] = bi0; c[nt][2] = bi1; c[nt][3] = bi1; }
#pragma unroll
                for (int ks = 0; ks < 4; ks++) {
                    uint32_t aa[4];
                    lda(aa, smc + WK_OFF, mt, ks, lane);
                    mma_bf16(c[0], aa[0], aa[1], aa[2], aa[3], bb[ks][0], bb[ks][1]);
                    mma_bf16(c[1], aa[0], aa[1], aa[2], aa[3], bb[ks][2], bb[ks][3]);
                }
#pragma unroll
                for (int nt = 0; nt < 2; nt++) {
                    *(uint32_t*)(smc + OS0_OFF + o * OPITCH + ncolb + nt * 16)
                        = packbf(__float2bfloat16(c[nt][0]), __float2bfloat16(c[nt][1]));
                    *(uint32_t*)(smc + OS0_OFF + (o + 8) * OPITCH + ncolb + nt * 16)
                        = packbf(__float2bfloat16(c[nt][2]), __float2bfloat16(c[nt][3]));
                }
            }
        }
        __syncthreads();
        // ---- K writeout (coalesced) ----
        {
            __nv_bfloat16* Ko = g_kb[br] + pbase;
#pragma unroll
            for (int i = 0; i < 4; i++) {
                int idx = t + i * 256;
                int row = idx >> 4, seg = idx & 15;
                uint4 v = *(const uint4*)(smc + OS0_OFF + row * OPITCH + seg * 16);
                *reinterpret_cast<uint4*>(Ko + (long)row * CN + n0 + seg * 8) = v;
            }
        }
        __syncthreads();

        // ================= V pass (split compute) -> OS0 as fp16 =================
        {
            uint32_t bh[4][4], bl[4][4];
#pragma unroll
            for (int ks = 0; ks < 4; ks++) {
                ldmx4(bh[ks][0], bh[ks][1], bh[ks][2], bh[ks][3], tb0 + ks * 32);
                ldmx4(bl[ks][0], bl[ks][1], bl[ks][2], bl[ks][3], tb1 + ks * 32);
            }
#pragma unroll
            for (int mt = 0; mt < 4; mt++) {
                int o = mt * 16 + (lane >> 2);
                float bi0 = __ldg(vbias + o), bi1 = __ldg(vbias + o + 8);
                float c[2][4];
#pragma unroll
                for (int nt = 0; nt < 2; nt++) { c[nt][0] = bi0; c[nt][1] = bi0; c[nt][2] = bi1; c[nt][3] = bi1; }
#pragma unroll
                for (int ks = 0; ks < 4; ks++) {
                    uint32_t ah[4], al[4];
                    lda(ah, smc + WVH_OFF, mt, ks, lane);
                    lda(al, smc + WVL_OFF, mt, ks, lane);
                    mma_bf16(c[0], ah[0], ah[1], ah[2], ah[3], bh[ks][0], bh[ks][1]);
                    mma_bf16(c[1], ah[0], ah[1], ah[2], ah[3], bh[ks][2], bh[ks][3]);
                    mma_bf16(c[0], ah[0], ah[1], ah[2], ah[3], bl[ks][0], bl[ks][1]);
                    mma_bf16(c[1], ah[0], ah[1], ah[2], ah[3], bl[ks][2], bl[ks][3]);
                    mma_bf16(c[0], al[0], al[1], al[2], al[3], bh[ks][0], bh[ks][1]);
                    mma_bf16(c[1], al[0], al[1], al[2], al[3], bh[ks][2], bh[ks][3]);
                }
#pragma unroll
                for (int nt = 0; nt < 2; nt++) {
                    *(uint32_t*)(smc + OS0_OFF + o * OPITCH + ncolb + nt * 16)
                        = packf16(c[nt][0], c[nt][1]);
                    *(uint32_t*)(smc + OS0_OFF + (o + 8) * OPITCH + ncolb + nt * 16)
                        = packf16(c[nt][2], c[nt][3]);
                }
            }
        }
        __syncthreads();
        // ---- V writeout (coalesced, fp16) + stage rssi -> T0 ----
        {
            __half* Vo = g_vf[br] + pbase;
#pragma unroll
            for (int i = 0; i < 4; i++) {
                int idx = t + i * 256;
                int row = idx >> 4, seg = idx & 15;
                uint4 v = *(const uint4*)(smc + OS0_OFF + row * OPITCH + seg * 16);
                *reinterpret_cast<uint4*>(Vo + (long)row * CN + n0 + seg * 8) = v;
            }
#pragma unroll
            for (int j = 0; j < 4; j++) {
                int c0 = (wid * 4 + j) * 2;
                const float* rr0 = R + pbase + (long)c0 * CN + n0;
                const float* rr1 = R + pbase + (long)(c0 + 1) * CN + n0;
#pragma unroll
                for (int nch = 0; nch < 4; nch++) {
                    int n = nch * 32 + lane;
                    *(uint32_t*)(smc + T0_OFF + n * WPITCH + c0 * 2) =
                        packbf(__float2bfloat16(rr0[n]), __float2bfloat16(rr1[n]));
                }
            }
        }
        __syncthreads();

        // ================= Q pass (B = T0 = rssi) -> OS0 =================
        {
            uint32_t bb[4][4];
#pragma unroll
            for (int ks = 0; ks < 4; ks++)
                ldmx4(bb[ks][0], bb[ks][1], bb[ks][2], bb[ks][3], tb0 + ks * 32);
#pragma unroll
            for (int mt = 0; mt < 4; mt++) {
                int o = mt * 16 + (lane >> 2);
                float bi0 = __ldg(qbias + o), bi1 = __ldg(qbias + o + 8);
                float c[2][4];
#pragma unroll
                for (int nt = 0; nt < 2; nt++) { c[nt][0] = bi0; c[nt][1] = bi0; c[nt][2] = bi1; c[nt][3] = bi1; }
#pragma unroll
                for (int ks = 0; ks < 4; ks++) {
                    uint32_t aa[4];
                    lda(aa, smc + WQ_OFF, mt, ks, lane);
                    mma_bf16(c[0], aa[0], aa[1], aa[2], aa[3], bb[ks][0], bb[ks][1]);
                    mma_bf16(c[1], aa[0], aa[1], aa[2], aa[3], bb[ks][2], bb[ks][3]);
                }
#pragma unroll
                for (int nt = 0; nt < 2; nt++) {
                    *(uint32_t*)(smc + OS0_OFF + o * OPITCH + ncolb + nt * 16)
                        = packbf(__float2bfloat16(c[nt][0]), __float2bfloat16(c[nt][1]));
                    *(uint32_t*)(smc + OS0_OFF + (o + 8) * OPITCH + ncolb + nt * 16)
                        = packbf(__float2bfloat16(c[nt][2]), __float2bfloat16(c[nt][3]));
                }
            }
        }
        __syncthreads();
        // ---- Q writeout (coalesced) ----
        {
            __nv_bfloat16* Qo = g_qb[br] + pbase;
#pragma unroll
            for (int i = 0; i < 4; i++) {
                int idx = t + i * 256;
                int row = idx >> 4, seg = idx & 15;
                uint4 v = *(const uint4*)(smc + OS0_OFF + row * OPITCH + seg * 16);
                *reinterpret_cast<uint4*>(Qo + (long)row * CN + n0 + seg * 8) = v;
            }
        }
    }
}

// ============================================================
// Attention: GEMM1 bf16, GEMM2 single-pass fp16 (P fp16 x V fp16).
// ============================================================
#define PITCHB 272
#define TILEB (128*PITCHB)
#define K_OFF 0
#define VF_OFF TILEB
#define ATTN_SMEM (2*TILEB + 64)

__device__ __forceinline__ void stage_tile(const void* __restrict__ g,
                                           char* smem, int off, int t)
{
    const float4* src = reinterpret_cast<const float4*>(g);
#pragma unroll
    for (int i = 0; i < 8; i++) {
        int idx = t + i * 256;
        int row = idx >> 4, seg = idx & 15;
        *reinterpret_cast<float4*>(smem + off + row * PITCHB + seg * 16) = src[idx];
    }
}

__global__ __launch_bounds__(256, 1) void attn_kernel()
{
    extern __shared__ char smc[];
    uint32_t smb = smem_to_u32(smc);
    int t = threadIdx.x, lane = t & 31, wid = t >> 5;
    int q = lane & 3, gid = lane >> 2;
    int bc = blockIdx.x;
    long base = (long)bc * CN;
    const float sc = 0.088388347648318447f;
    int r0 = wid * 16 + gid;

    int lrow  = (lane & 7) + ((lane >> 4) << 3);
    int lcolb = ((lane >> 3) & 1) * 16;
    int trow  = (lane & 7) + (((lane >> 3) & 1) << 3);
    int tcolb = ((lane >> 4) & 1) * 16;

    float oacc[16][4];
#pragma unroll
    for (int nt = 0; nt < 16; nt++)
#pragma unroll
        for (int j = 0; j < 4; j++) oacc[nt][j] = 0.f;

#pragma unroll 1
    for (int br = 0; br < 2; br++) {
        const __nv_bfloat16* Qp = g_qb[br] + base;

        __syncthreads();
        stage_tile(g_kb[br] + base, smc, K_OFF, t);
        stage_tile(g_vf[br] + base, smc, VF_OFF, t);
        __syncthreads();

        float sacc[16][4];
#pragma unroll
        for (int nt = 0; nt < 16; nt++)
#pragma unroll
            for (int j = 0; j < 4; j++) sacc[nt][j] = 0.f;

#pragma unroll
        for (int st = 0; st < 8; st++) {
            int c0 = st * 16 + q * 2;
            uint32_t a0 = ld32(Qp + (long)r0 * 128 + c0);
            uint32_t a1 = ld32(Qp + (long)(r0 + 8) * 128 + c0);
            uint32_t a2 = ld32(Qp + (long)r0 * 128 + c0 + 8);
            uint32_t a3 = ld32(Qp + (long)(r0 + 8) * 128 + c0 + 8);
            uint32_t kb = smb + K_OFF + (uint32_t)lrow * PITCHB + st * 32 + lcolb;
#pragma unroll
            for (int np = 0; np < 8; np++) {
                uint32_t b0, b1, b2, b3;
                ldmx4(b0, b1, b2, b3, kb + np * (16 * PITCHB));
                mma_bf16(sacc[2*np  ], a0, a1, a2, a3, b0, b1);
                mma_bf16(sacc[2*np+1], a0, a1, a2, a3, b2, b3);
            }
        }

        float m0 = -1e30f, m1 = -1e30f;
#pragma unroll
        for (int nt = 0; nt < 16; nt++) {
            m0 = fmaxf(m0, fmaxf(sacc[nt][0], sacc[nt][1]));
            m1 = fmaxf(m1, fmaxf(sacc[nt][2], sacc[nt][3]));
        }
        m0 = fmaxf(m0, __shfl_xor_sync(0xffffffffu, m0, 1));
        m0 = fmaxf(m0, __shfl_xor_sync(0xffffffffu, m0, 2));
        m1 = fmaxf(m1, __shfl_xor_sync(0xffffffffu, m1, 1));
        m1 = fmaxf(m1, __shfl_xor_sync(0xffffffffu, m1, 2));

        float s0 = 0.f, s1 = 0.f;
#pragma unroll
        for (int nt = 0; nt < 16; nt++) {
            sacc[nt][0] = __expf((sacc[nt][0] - m0) * sc);
            sacc[nt][1] = __expf((sacc[nt][1] - m0) * sc);
            sacc[nt][2] = __expf((sacc[nt][2] - m1) * sc);
            sacc[nt][3] = __expf((sacc[nt][3] - m1) * sc);
            s0 += sacc[nt][0] + sacc[nt][1];
            s1 += sacc[nt][2] + sacc[nt][3];
        }
        s0 += __shfl_xor_sync(0xffffffffu, s0, 1);
        s0 += __shfl_xor_sync(0xffffffffu, s0, 2);
        s1 += __shfl_xor_sync(0xffffffffu, s1, 1);
        s1 += __shfl_xor_sync(0xffffffffu, s1, 2);
        float inv0 = 1.f / s0, inv1 = 1.f / s1;

        // ---- GEMM2 single-pass fp16: O += P16 * V16 ----
#pragma unroll
        for (int st = 0; st < 8; st++) {
            uint32_t pa0 = packf16(sacc[2*st  ][0] * inv0, sacc[2*st  ][1] * inv0);
            uint32_t pa1 = packf16(sacc[2*st  ][2] * inv1, sacc[2*st  ][3] * inv1);
            uint32_t pa2 = packf16(sacc[2*st+1][0] * inv0, sacc[2*st+1][1] * inv0);
            uint32_t pa3 = packf16(sacc[2*st+1][2] * inv1, sacc[2*st+1][3] * inv1);

            uint32_t vb = (uint32_t)(st * 16 + trow) * PITCHB + tcolb;
#pragma unroll
            for (int np = 0; np < 8; np++) {
                uint32_t h0, h1, h2, h3;
                ldmx4t(h0, h1, h2, h3, smb + VF_OFF + vb + np * 32);
                mma_f16h(oacc[2*np  ], pa0, pa1, pa2, pa3, h0, h1);
                mma_f16h(oacc[2*np+1], pa0, pa1, pa2, pa3, h2, h3);
            }
        }
    }

    float lsum = 0.f, lsq = 0.f;
    float* F = g_fused + base;
#pragma unroll
    for (int nt = 0; nt < 16; nt++) {
        int c = nt * 8 + q * 2;
        float2 u = make_float2(oacc[nt][0], oacc[nt][1]);
        float2 v = make_float2(oacc[nt][2], oacc[nt][3]);
        *reinterpret_cast<float2*>(F + (long)r0 * 128 + c) = u;
        *reinterpret_cast<float2*>(F + (long)(r0 + 8) * 128 + c) = v;
        lsum += u.x + u.y + v.x + v.y;
        lsq  += u.x*u.x + u.y*u.y + v.x*v.x + v.y*v.y;
    }
#pragma unroll
    for (int o = 16; o; o >>= 1) {
        lsum += __shfl_xor_sync(0xffffffffu, lsum, o);
        lsq  += __shfl_xor_sync(0xffffffffu, lsq , o);
    }
    float* red = reinterpret_cast<float*>(smc + 2 * TILEB);
    if (lane == 0) { red[wid] = lsum; red[8 + wid] = lsq; }
    __syncthreads();
    if (t == 0) {
        float s = 0.f, qq = 0.f;
        for (int w2 = 0; w2 < 8; w2++) { s += red[w2]; qq += red[8 + w2]; }
        g_psum[bc] = s; g_psumsq[bc] = qq;
    }
}

// ============================================================
// BN stats + normalize
// ============================================================
__global__ void stats_kernel(const float* __restrict__ gamma, const float* __restrict__ beta)
{
    int c = threadIdx.x;
    if (c < CC) {
        double s = 0.0, q = 0.0;
        for (int b = 0; b < CB; b++) {
            s += (double)g_psum[b * CC + c];
            q += (double)g_psumsq[b * CC + c];
        }
        double nn = (double)CB * (double)CN;
        double mean = s / nn;
        double var = q / nn - mean * mean;
        float a = (float)((double)gamma[c] * rsqrt(var + 1e-5));
        g_scale[c] = a;
        g_shift[c] = beta[c] - (float)mean * a;
    }
}

__global__ void norm_kernel(float* __restrict__ out)
{
    long i4 = (long)blockIdx.x * blockDim.x + threadIdx.x;
    if (i4 < (TOTE / 4)) {
        int c = (int)((i4 >> 12) & 63);
        float a = g_scale[c], sh = g_shift[c];
        float4 f = reinterpret_cast<const float4*>(g_fused)[i4];
        float4 r;
        r.x = fmaxf(0.f, fmaf(f.x, a, sh));
        r.y = fmaxf(0.f, fmaf(f.y, a, sh));
        r.z = fmaxf(0.f, fmaf(f.z, a, sh));
        r.w = fmaxf(0.f, fmaf(f.w, a, sh));
        reinterpret_cast<float4*>(out)[i4] = r;
    }
}

// ============================================================
// Launch
// ============================================================
extern "C" void kernel_launch(void* const* d_in, const int* in_sizes, int n_in,
                              void* d_out, int out_size)
{
    const float* x1    = (const float*)d_in[0];
    const float* x2    = (const float*)d_in[1];
    const float* rssi1 = (const float*)d_in[2];
    const float* rssi2 = (const float*)d_in[3];
    const float* qw    = (const float*)d_in[4];
    const float* qb    = (const float*)d_in[5];
    const float* kw    = (const float*)d_in[6];
    const float* kb    = (const float*)d_in[7];
    const float* vw    = (const float*)d_in[8];
    const float* vb    = (const float*)d_in[9];
    const float* gamma = (const float*)d_in[10];
    const float* beta  = (const float*)d_in[11];
    float* out = (float*)d_out;

    cudaFuncSetAttribute(proj_mma_kernel, cudaFuncAttributeMaxDynamicSharedMemorySize, PROJ2_SMEM);
    cudaFuncSetAttribute(attn_kernel, cudaFuncAttributeMaxDynamicSharedMemorySize, ATTN_SMEM);

    proj_mma_kernel<<<dim3(CN / 128, CB), 256, PROJ2_SMEM>>>(
        x1, x2, rssi1, rssi2, qw, qb, kw, kb, vw, vb);
    attn_kernel<<<CB * CC, 256, ATTN_SMEM>>>();
    stats_kernel<<<1, 64>>>(gamma, beta);
    norm_kernel<<<TOTE / 4 / 256, 256>>>(out);
}

// round 15
// speedup vs baseline: 4.6859x; 1.1270x over previous
#include <cuda_runtime.h>
#include <cuda_bf16.h>
#include <cuda_fp16.h>
#include <cstdint>

// Problem constants
#define CB 16
#define CC 64
#define CH 128
#define CW 128
#define CN (CH*CW)
#define PLANE ((long)CC*CN)
#define TOTE 16777216

// -------- scratch (device globals) --------
__device__ __half  g_qf[2][TOTE];    // Q fp16 [h,w]
__device__ __half  g_kf[2][TOTE];    // K fp16 [g,w]
__device__ __half  g_vf[2][TOTE];    // V fp16, natural [g,w]
__device__ float   g_fused[TOTE];
__device__ float   g_psum[CB*CC];
__device__ float   g_psumsq[CB*CC];
__device__ float   g_scale[CC];
__device__ float   g_shift[CC];

// ============================================================
// mma.sync / ldmatrix helpers (sm_80 PTX; safe on generic compute_103)
// ============================================================
__device__ __forceinline__ void mma_f16h(float d[4],
                                         uint32_t a0, uint32_t a1, uint32_t a2, uint32_t a3,
                                         uint32_t b0, uint32_t b1)
{
    asm volatile(
        "mma.sync.aligned.m16n8k16.row.col.f32.f16.f16.f32 "
        "{%0,%1,%2,%3}, {%4,%5,%6,%7}, {%8,%9}, {%0,%1,%2,%3};"
        : "+f"(d[0]), "+f"(d[1]), "+f"(d[2]), "+f"(d[3])
        : "r"(a0), "r"(a1), "r"(a2), "r"(a3), "r"(b0), "r"(b1));
}

__device__ __forceinline__ void ldmx4(uint32_t& b0, uint32_t& b1, uint32_t& b2, uint32_t& b3,
                                      uint32_t addr)
{
    asm volatile("ldmatrix.sync.aligned.m8n8.x4.shared.b16 {%0,%1,%2,%3}, [%4];"
                 : "=r"(b0), "=r"(b1), "=r"(b2), "=r"(b3) : "r"(addr));
}

__device__ __forceinline__ void ldmx4t(uint32_t& b0, uint32_t& b1, uint32_t& b2, uint32_t& b3,
                                       uint32_t addr)
{
    asm volatile("ldmatrix.sync.aligned.m8n8.x4.trans.shared.b16 {%0,%1,%2,%3}, [%4];"
                 : "=r"(b0), "=r"(b1), "=r"(b2), "=r"(b3) : "r"(addr));
}

__device__ __forceinline__ uint32_t smem_to_u32(const void* p) {
    uint32_t a;
    asm("{ .reg .u64 tmp; cvta.to.shared.u64 tmp, %1; cvt.u32.u64 %0, tmp; }" : "=r"(a) : "l"(p));
    return a;
}

__device__ __forceinline__ uint32_t ld32h(const __half* p) {
    return *reinterpret_cast<const uint32_t*>(p);
}

__device__ __forceinline__ uint32_t packf16(float x, float y) {
    __half2 h = __float22half2_rn(make_float2(x, y));   // x -> low 16 bits
    return *reinterpret_cast<uint32_t*>(&h);
}

// ============================================================
// Fused projection via mma.sync, all-fp16 single-pass, coalesced writeout.
// CTA: 256 thr, 128 spatial cols. 62KB smem -> 2 CTA/SM.
// ============================================================
#define WPITCH 144            // 64 fp16 cols + pad (9 x 16B)
#define OPITCH 272            // 128 fp16 cols + pad (17 x 16B)
#define WQ_OFF  0
#define WK_OFF  9216
#define WV_OFF  18432
#define T0_OFF  27648
#define OS0_OFF 46080
#define PROJ2_SMEM 63488

// A-fragment (weights) from smem W[o][c], row-major, WPITCH bytes/row.
__device__ __forceinline__ void lda(uint32_t a[4], const char* smW, int mt, int ks, int lane) {
    const char* p = smW + (mt * 16 + (lane >> 2)) * WPITCH + ks * 32 + (lane & 3) * 4;
    a[0] = *(const uint32_t*)p;
    a[1] = *(const uint32_t*)(p + 8 * WPITCH);
    a[2] = *(const uint32_t*)(p + 16);
    a[3] = *(const uint32_t*)(p + 8 * WPITCH + 16);
}

__global__ __launch_bounds__(256, 2) void proj_mma_kernel(
    const float* __restrict__ x1, const float* __restrict__ x2,
    const float* __restrict__ rssi1, const float* __restrict__ rssi2,
    const float* __restrict__ qw, const float* __restrict__ qbias,
    const float* __restrict__ kw, const float* __restrict__ kbias,
    const float* __restrict__ vw, const float* __restrict__ vbias)
{
    extern __shared__ char smc[];
    uint32_t smb = smem_to_u32(smc);
    int t = threadIdx.x, lane = t & 31, wid = t >> 5;
    int b = blockIdx.y;
    int n0 = blockIdx.x * 128;
    long pbase = (long)b * PLANE;

    // ---- stage weights once (fp16) ----
    for (int i = t; i < 1024; i += 256) {          // 1024 float4 per 64x64 matrix
        int o = i >> 4, c4 = i & 15;
        float4 wq = reinterpret_cast<const float4*>(qw)[i];
        float4 wk = reinterpret_cast<const float4*>(kw)[i];
        float4 wv = reinterpret_cast<const float4*>(vw)[i];
        char* rq = smc + WQ_OFF + o * WPITCH + c4 * 8;
        char* rk = smc + WK_OFF + o * WPITCH + c4 * 8;
        char* rv = smc + WV_OFF + o * WPITCH + c4 * 8;
        *(uint32_t*)(rq)     = packf16(wq.x, wq.y);
        *(uint32_t*)(rq + 4) = packf16(wq.z, wq.w);
        *(uint32_t*)(rk)     = packf16(wk.x, wk.y);
        *(uint32_t*)(rk + 4) = packf16(wk.z, wk.w);
        *(uint32_t*)(rv)     = packf16(wv.x, wv.y);
        *(uint32_t*)(rv + 4) = packf16(wv.z, wv.w);
    }

    int lrow  = (lane & 7) + ((lane >> 4) << 3);
    int lcolb = ((lane >> 3) & 1) * 16;
    uint32_t tb0 = smb + T0_OFF + (uint32_t)(wid * 16 + lrow) * WPITCH + lcolb;
    int ncolb = (wid * 16 + (lane & 3) * 2) * 2;   // byte col base in OS tile

#pragma unroll 1
    for (int br = 0; br < 2; br++) {
        const float* X = br ? x2 : x1;
        const float* R = br ? rssi2 : rssi1;
        __syncthreads();   // weights / previous-branch buffers consumed

        // ---- stage x -> T0 fp16, transposed [n][c] ----
#pragma unroll
        for (int j = 0; j < 4; j++) {
            int c0 = (wid * 4 + j) * 2;
            const float* xr0 = X + pbase + (long)c0 * CN + n0;
            const float* xr1 = X + pbase + (long)(c0 + 1) * CN + n0;
#pragma unroll
            for (int nch = 0; nch < 4; nch++) {
                int n = nch * 32 + lane;
                *(uint32_t*)(smc + T0_OFF + n * WPITCH + c0 * 2) = packf16(xr0[n], xr1[n]);
            }
        }
        __syncthreads();

        // B-fragments of x: loaded once, reused for K and V passes
        uint32_t bb[4][4];
#pragma unroll
        for (int ks = 0; ks < 4; ks++)
            ldmx4(bb[ks][0], bb[ks][1], bb[ks][2], bb[ks][3], tb0 + ks * 32);

        // ================= K pass -> OS0 =================
#pragma unroll
        for (int mt = 0; mt < 4; mt++) {
            int o = mt * 16 + (lane >> 2);
            float bi0 = __ldg(kbias + o), bi1 = __ldg(kbias + o + 8);
            float c[2][4];
#pragma unroll
            for (int nt = 0; nt < 2; nt++) { c[nt][0] = bi0; c[nt][1] = bi0; c[nt][2] = bi1; c[nt][3] = bi1; }
#pragma unroll
            for (int ks = 0; ks < 4; ks++) {
                uint32_t aa[4];
                lda(aa, smc + WK_OFF, mt, ks, lane);
                mma_f16h(c[0], aa[0], aa[1], aa[2], aa[3], bb[ks][0], bb[ks][1]);
                mma_f16h(c[1], aa[0], aa[1], aa[2], aa[3], bb[ks][2], bb[ks][3]);
            }
#pragma unroll
            for (int nt = 0; nt < 2; nt++) {
                *(uint32_t*)(smc + OS0_OFF + o * OPITCH + ncolb + nt * 16)
                    = packf16(c[nt][0], c[nt][1]);
                *(uint32_t*)(smc + OS0_OFF + (o + 8) * OPITCH + ncolb + nt * 16)
                    = packf16(c[nt][2], c[nt][3]);
            }
        }
        __syncthreads();
        // ---- K writeout (coalesced) ----
        {
            __half* Ko = g_kf[br] + pbase;
#pragma unroll
            for (int i = 0; i < 4; i++) {
                int idx = t + i * 256;
                int row = idx >> 4, seg = idx & 15;
                uint4 v = *(const uint4*)(smc + OS0_OFF + row * OPITCH + seg * 16);
                *reinterpret_cast<uint4*>(Ko + (long)row * CN + n0 + seg * 8) = v;
            }
        }
        __syncthreads();

        // ================= V pass (reuses bb) -> OS0 =================
#pragma unroll
        for (int mt = 0; mt < 4; mt++) {
            int o = mt * 16 + (lane >> 2);
            float bi0 = __ldg(vbias + o), bi1 = __ldg(vbias + o + 8);
            float c[2][4];
#pragma unroll
            for (int nt = 0; nt < 2; nt++) { c[nt][0] = bi0; c[nt][1] = bi0; c[nt][2] = bi1; c[nt][3] = bi1; }
#pragma unroll
            for (int ks = 0; ks < 4; ks++) {
                uint32_t aa[4];
                lda(aa, smc + WV_OFF, mt, ks, lane);
                mma_f16h(c[0], aa[0], aa[1], aa[2], aa[3], bb[ks][0], bb[ks][1]);
                mma_f16h(c[1], aa[0], aa[1], aa[2], aa[3], bb[ks][2], bb[ks][3]);
            }
#pragma unroll
            for (int nt = 0; nt < 2; nt++) {
                *(uint32_t*)(smc + OS0_OFF + o * OPITCH + ncolb + nt * 16)
                    = packf16(c[nt][0], c[nt][1]);
                *(uint32_t*)(smc + OS0_OFF + (o + 8) * OPITCH + ncolb + nt * 16)
                    = packf16(c[nt][2], c[nt][3]);
            }
        }
        __syncthreads();
        // ---- V writeout (coalesced) + stage rssi -> T0 ----
        {
            __half* Vo = g_vf[br] + pbase;
#pragma unroll
            for (int i = 0; i < 4; i++) {
                int idx = t + i * 256;
                int row = idx >> 4, seg = idx & 15;
                uint4 v = *(const uint4*)(smc + OS0_OFF + row * OPITCH + seg * 16);
                *reinterpret_cast<uint4*>(Vo + (long)row * CN + n0 + seg * 8) = v;
            }
#pragma unroll
            for (int j = 0; j < 4; j++) {
                int c0 = (wid * 4 + j) * 2;
                const float* rr0 = R + pbase + (long)c0 * CN + n0;
                const float* rr1 = R + pbase + (long)(c0 + 1) * CN + n0;
#pragma unroll
                for (int nch = 0; nch < 4; nch++) {
                    int n = nch * 32 + lane;
                    *(uint32_t*)(smc + T0_OFF + n * WPITCH + c0 * 2) = packf16(rr0[n], rr1[n]);
                }
            }
        }
        __syncthreads();

        // ================= Q pass (B = T0 = rssi) -> OS0 =================
        {
            uint32_t qb[4][4];
#pragma unroll
            for (int ks = 0; ks < 4; ks++)
                ldmx4(qb[ks][0], qb[ks][1], qb[ks][2], qb[ks][3], tb0 + ks * 32);
#pragma unroll
            for (int mt = 0; mt < 4; mt++) {
                int o = mt * 16 + (lane >> 2);
                float bi0 = __ldg(qbias + o), bi1 = __ldg(qbias + o + 8);
                float c[2][4];
#pragma unroll
                for (int nt = 0; nt < 2; nt++) { c[nt][0] = bi0; c[nt][1] = bi0; c[nt][2] = bi1; c[nt][3] = bi1; }
#pragma unroll
                for (int ks = 0; ks < 4; ks++) {
                    uint32_t aa[4];
                    lda(aa, smc + WQ_OFF, mt, ks, lane);
                    mma_f16h(c[0], aa[0], aa[1], aa[2], aa[3], qb[ks][0], qb[ks][1]);
                    mma_f16h(c[1], aa[0], aa[1], aa[2], aa[3], qb[ks][2], qb[ks][3]);
                }
#pragma unroll
                for (int nt = 0; nt < 2; nt++) {
                    *(uint32_t*)(smc + OS0_OFF + o * OPITCH + ncolb + nt * 16)
                        = packf16(c[nt][0], c[nt][1]);
                    *(uint32_t*)(smc + OS0_OFF + (o + 8) * OPITCH + ncolb + nt * 16)
                        = packf16(c[nt][2], c[nt][3]);
                }
            }
        }
        __syncthreads();
        // ---- Q writeout (coalesced) ----
        {
            __half* Qo = g_qf[br] + pbase;
#pragma unroll
            for (int i = 0; i < 4; i++) {
                int idx = t + i * 256;
                int row = idx >> 4, seg = idx & 15;
                uint4 v = *(const uint4*)(smc + OS0_OFF + row * OPITCH + seg * 16);
                *reinterpret_cast<uint4*>(Qo + (long)row * CN + n0 + seg * 8) = v;
            }
        }
    }
}

// ============================================================
// Attention: GEMM1 fp16, GEMM2 fp16 (unchanged structure, verified R14).
// ============================================================
#define PITCHB 272
#define TILEB (128*PITCHB)
#define K_OFF 0
#define VF_OFF TILEB
#define ATTN_SMEM (2*TILEB + 64)

__device__ __forceinline__ void stage_tile(const void* __restrict__ g,
                                           char* smem, int off, int t)
{
    const float4* src = reinterpret_cast<const float4*>(g);
#pragma unroll
    for (int i = 0; i < 8; i++) {
        int idx = t + i * 256;
        int row = idx >> 4, seg = idx & 15;
        *reinterpret_cast<float4*>(smem + off + row * PITCHB + seg * 16) = src[idx];
    }
}

__global__ __launch_bounds__(256, 1) void attn_kernel()
{
    extern __shared__ char smc[];
    uint32_t smb = smem_to_u32(smc);
    int t = threadIdx.x, lane = t & 31, wid = t >> 5;
    int q = lane & 3, gid = lane >> 2;
    int bc = blockIdx.x;
    long base = (long)bc * CN;
    const float sc = 0.088388347648318447f;
    int r0 = wid * 16 + gid;

    int lrow  = (lane & 7) + ((lane >> 4) << 3);
    int lcolb = ((lane >> 3) & 1) * 16;
    int trow  = (lane & 7) + (((lane >> 3) & 1) << 3);
    int tcolb = ((lane >> 4) & 1) * 16;

    float oacc[16][4];
#pragma unroll
    for (int nt = 0; nt < 16; nt++)
#pragma unroll
        for (int j = 0; j < 4; j++) oacc[nt][j] = 0.f;

#pragma unroll 1
    for (int br = 0; br < 2; br++) {
        const __half* Qp = g_qf[br] + base;

        __syncthreads();
        stage_tile(g_kf[br] + base, smc, K_OFF, t);
        stage_tile(g_vf[br] + base, smc, VF_OFF, t);
        __syncthreads();

        float sacc[16][4];
#pragma unroll
        for (int nt = 0; nt < 16; nt++)
#pragma unroll
            for (int j = 0; j < 4; j++) sacc[nt][j] = 0.f;

#pragma unroll
        for (int st = 0; st < 8; st++) {
            int c0 = st * 16 + q * 2;
            uint32_t a0 = ld32h(Qp + (long)r0 * 128 + c0);
            uint32_t a1 = ld32h(Qp + (long)(r0 + 8) * 128 + c0);
            uint32_t a2 = ld32h(Qp + (long)r0 * 128 + c0 + 8);
            uint32_t a3 = ld32h(Qp + (long)(r0 + 8) * 128 + c0 + 8);
            uint32_t kb = smb + K_OFF + (uint32_t)lrow * PITCHB + st * 32 + lcolb;
#pragma unroll
            for (int np = 0; np < 8; np++) {
                uint32_t b0, b1, b2, b3;
                ldmx4(b0, b1, b2, b3, kb + np * (16 * PITCHB));
                mma_f16h(sacc[2*np  ], a0, a1, a2, a3, b0, b1);
                mma_f16h(sacc[2*np+1], a0, a1, a2, a3, b2, b3);
            }
        }

        float m0 = -1e30f, m1 = -1e30f;
#pragma unroll
        for (int nt = 0; nt < 16; nt++) {
            m0 = fmaxf(m0, fmaxf(sacc[nt][0], sacc[nt][1]));
            m1 = fmaxf(m1, fmaxf(sacc[nt][2], sacc[nt][3]));
        }
        m0 = fmaxf(m0, __shfl_xor_sync(0xffffffffu, m0, 1));
        m0 = fmaxf(m0, __shfl_xor_sync(0xffffffffu, m0, 2));
        m1 = fmaxf(m1, __shfl_xor_sync(0xffffffffu, m1, 1));
        m1 = fmaxf(m1, __shfl_xor_sync(0xffffffffu, m1, 2));

        float s0 = 0.f, s1 = 0.f;
#pragma unroll
        for (int nt = 0; nt < 16; nt++) {
            sacc[nt][0] = __expf((sacc[nt][0] - m0) * sc);
            sacc[nt][1] = __expf((sacc[nt][1] - m0) * sc);
            sacc[nt][2] = __expf((sacc[nt][2] - m1) * sc);
            sacc[nt][3] = __expf((sacc[nt][3] - m1) * sc);
            s0 += sacc[nt][0] + sacc[nt][1];
            s1 += sacc[nt][2] + sacc[nt][3];
        }
        s0 += __shfl_xor_sync(0xffffffffu, s0, 1);
        s0 += __shfl_xor_sync(0xffffffffu, s0, 2);
        s1 += __shfl_xor_sync(0xffffffffu, s1, 1);
        s1 += __shfl_xor_sync(0xffffffffu, s1, 2);
        float inv0 = 1.f / s0, inv1 = 1.f / s1;

        // ---- GEMM2 single-pass fp16 ----
#pragma unroll
        for (int st = 0; st < 8; st++) {
            uint32_t pa0 = packf16(sacc[2*st  ][0] * inv0, sacc[2*st  ][1] * inv0);
            uint32_t pa1 = packf16(sacc[2*st  ][2] * inv1, sacc[2*st  ][3] * inv1);
            uint32_t pa2 = packf16(sacc[2*st+1][0] * inv0, sacc[2*st+1][1] * inv0);
            uint32_t pa3 = packf16(sacc[2*st+1][2] * inv1, sacc[2*st+1][3] * inv1);

            uint32_t vb = (uint32_t)(st * 16 + trow) * PITCHB + tcolb;
#pragma unroll
            for (int np = 0; np < 8; np++) {
                uint32_t h0, h1, h2, h3;
                ldmx4t(h0, h1, h2, h3, smb + VF_OFF + vb + np * 32);
                mma_f16h(oacc[2*np  ], pa0, pa1, pa2, pa3, h0, h1);
                mma_f16h(oacc[2*np+1], pa0, pa1, pa2, pa3, h2, h3);
            }
        }
    }

    float lsum = 0.f, lsq = 0.f;
    float* F = g_fused + base;
#pragma unroll
    for (int nt = 0; nt < 16; nt++) {
        int c = nt * 8 + q * 2;
        float2 u = make_float2(oacc[nt][0], oacc[nt][1]);
        float2 v = make_float2(oacc[nt][2], oacc[nt][3]);
        *reinterpret_cast<float2*>(F + (long)r0 * 128 + c) = u;
        *reinterpret_cast<float2*>(F + (long)(r0 + 8) * 128 + c) = v;
        lsum += u.x + u.y + v.x + v.y;
        lsq  += u.x*u.x + u.y*u.y + v.x*v.x + v.y*v.y;
    }
#pragma unroll
    for (int o = 16; o; o >>= 1) {
        lsum += __shfl_xor_sync(0xffffffffu, lsum, o);
        lsq  += __shfl_xor_sync(0xffffffffu, lsq , o);
    }
    float* red = reinterpret_cast<float*>(smc + 2 * TILEB);
    if (lane == 0) { red[wid] = lsum; red[8 + wid] = lsq; }
    __syncthreads();
    if (t == 0) {
        float s = 0.f, qq = 0.f;
        for (int w2 = 0; w2 < 8; w2++) { s += red[w2]; qq += red[8 + w2]; }
        g_psum[bc] = s; g_psumsq[bc] = qq;
    }
}

// ============================================================
// BN stats + normalize
// ============================================================
__global__ void stats_kernel(const float* __restrict__ gamma, const float* __restrict__ beta)
{
    int c = threadIdx.x;
    if (c < CC) {
        double s = 0.0, q = 0.0;
        for (int b = 0; b < CB; b++) {
            s += (double)g_psum[b * CC + c];
            q += (double)g_psumsq[b * CC + c];
        }
        double nn = (double)CB * (double)CN;
        double mean = s / nn;
        double var = q / nn - mean * mean;
        float a = (float)((double)gamma[c] * rsqrt(var + 1e-5));
        g_scale[c] = a;
        g_shift[c] = beta[c] - (float)mean * a;
    }
}

__global__ void norm_kernel(float* __restrict__ out)
{
    long i4 = (long)blockIdx.x * blockDim.x + threadIdx.x;
    if (i4 < (TOTE / 4)) {
        int c = (int)((i4 >> 12) & 63);
        float a = g_scale[c], sh = g_shift[c];
        float4 f = reinterpret_cast<const float4*>(g_fused)[i4];
        float4 r;
        r.x = fmaxf(0.f, fmaf(f.x, a, sh));
        r.y = fmaxf(0.f, fmaf(f.y, a, sh));
        r.z = fmaxf(0.f, fmaf(f.z, a, sh));
        r.w = fmaxf(0.f, fmaf(f.w, a, sh));
        reinterpret_cast<float4*>(out)[i4] = r;
    }
}

// ============================================================
// Launch
// ============================================================
extern "C" void kernel_launch(void* const* d_in, const int* in_sizes, int n_in,
                              void* d_out, int out_size)
{
    const float* x1    = (const float*)d_in[0];
    const float* x2    = (const float*)d_in[1];
    const float* rssi1 = (const float*)d_in[2];
    const float* rssi2 = (const float*)d_in[3];
    const float* qw    = (const float*)d_in[4];
    const float* qb    = (const float*)d_in[5];
    const float* kw    = (const float*)d_in[6];
    const float* kb    = (const float*)d_in[7];
    const float* vw    = (const float*)d_in[8];
    const float* vb    = (const float*)d_in[9];
    const float* gamma = (const float*)d_in[10];
    const float* beta  = (const float*)d_in[11];
    float* out = (float*)d_out;

    cudaFuncSetAttribute(proj_mma_kernel, cudaFuncAttributeMaxDynamicSharedMemorySize, PROJ2_SMEM);
    cudaFuncSetAttribute(attn_kernel, cudaFuncAttributeMaxDynamicSharedMemorySize, ATTN_SMEM);

    proj_mma_kernel<<<dim3(CN / 128, CB), 256, PROJ2_SMEM>>>(
        x1, x2, rssi1, rssi2, qw, qb, kw, kb, vw, vb);
    attn_kernel<<<CB * CC, 256, ATTN_SMEM>>>();
    stats_kernel<<<1, 64>>>(gamma, beta);
    norm_kernel<<<TOTE / 4 / 256, 256>>>(out);
}